// round 14
// baseline (speedup 1.0000x reference)
#include <cuda_runtime.h>
#include <cuda_bf16.h>
#include <cuda_fp16.h>
#include <stdint.h>
#include <math.h>

// Problem constants (fixed by the dataset)
#define NN 100000
#define EE 3200000
#define FIN 128
#define HH  256
#define GG  64
#define HO  128   // H/2

typedef unsigned long long u64;

// ---------------- per-pass scratch (static device globals) --------------------
#define NH ((size_t)NN * HH)
__device__ __align__(16) __half g_a  [3][NH];                 // GEMM out (relu'd, gather source)
__device__ __align__(16) __half g_agg[3][NH];                 // pull out (GEMM A input)
__device__ __align__(16) __half g_xh [3][(size_t)NN * FIN];   // fp16 x
__device__ __align__(16) __half g_wt [256 * HH + 256 * FIN];  // fp16 WT: W1 [256][256], W0 [256][128]
__device__ float g_dinv [3][NN];
__device__ float g_dinv2[3][NN];
__device__ int   g_deg  [3][NN];
__device__ __align__(16) float g_psum[3][GG * HH];
__device__ int   g_pcnt[3][GG];
__device__ int   g_rowptr[3][NN + 1];
__device__ int   g_off[3][NN];
__device__ int   g_bsum[3][128];
__device__ int   g_bsum2[3][128];
__device__ __align__(16) int2 g_epack[3][EE];   // (src, coef-as-int)

// ---------------- helpers ----------------------------------------------------
__device__ __forceinline__ void red_add_v4(float4* addr, float4 v) {
    asm volatile("red.global.add.v4.f32 [%0], {%1,%2,%3,%4};"
                 :: "l"(addr), "f"(v.x), "f"(v.y), "f"(v.z), "f"(v.w)
                 : "memory");
}
__device__ __forceinline__ void hacc2(float4& a, float cf, uint2 v) {
    float2 x0 = __half22float2(*reinterpret_cast<const __half2*>(&v.x));
    float2 x1 = __half22float2(*reinterpret_cast<const __half2*>(&v.y));
    a.x = fmaf(cf, x0.x, a.x); a.y = fmaf(cf, x0.y, a.y);
    a.z = fmaf(cf, x1.x, a.z); a.w = fmaf(cf, x1.y, a.w);
}
__device__ __forceinline__ void hacc1(float2& a, float cf, uint32_t v) {
    float2 x = __half22float2(*reinterpret_cast<const __half2*>(&v));
    a.x = fmaf(cf, x.x, a.x); a.y = fmaf(cf, x.y, a.y);
}
__device__ __forceinline__ uint2 pack_half4(float4 v) {
    __half2 h0 = __float22half2_rn(make_float2(v.x, v.y));
    __half2 h1 = __float22half2_rn(make_float2(v.z, v.w));
    uint2 s;
    s.x = *reinterpret_cast<uint32_t*>(&h0);
    s.y = *reinterpret_cast<uint32_t*>(&h1);
    return s;
}
__device__ __forceinline__ float4 unpack_half4(uint2 s) {
    float2 a = __half22float2(*reinterpret_cast<const __half2*>(&s.x));
    float2 b = __half22float2(*reinterpret_cast<const __half2*>(&s.y));
    return make_float4(a.x, a.y, b.x, b.y);
}
__device__ __forceinline__ void mma16816(float* c, const uint32_t* a, const uint32_t* b) {
    asm volatile(
        "mma.sync.aligned.m16n8k16.row.col.f32.f16.f16.f32 "
        "{%0,%1,%2,%3}, {%4,%5,%6,%7}, {%8,%9}, {%0,%1,%2,%3};"
        : "+f"(c[0]), "+f"(c[1]), "+f"(c[2]), "+f"(c[3])
        : "r"(a[0]), "r"(a[1]), "r"(a[2]), "r"(a[3]), "r"(b[0]), "r"(b[1]));
}

// ---------------- per-pass setup ---------------------------------------------
__global__ void zero_kernel(int p) {
    int i = blockIdx.x * blockDim.x + threadIdx.x;
    if (i < NN)      { g_deg[p][i] = 0; g_off[p][i] = 0; }
    if (i < GG * HH) g_psum[p][i] = 0.f;
    if (i < GG)      g_pcnt[p][i] = 0;
}

// 4 edges per thread (EE % 4 == 0)
__global__ void deg_kernel(const int* __restrict__ dst, int p) {
    int e4 = (blockIdx.x * blockDim.x + threadIdx.x) * 4;
    if (e4 >= EE) return;
    int4 d = *reinterpret_cast<const int4*>(dst + e4);
    atomicAdd(&g_deg[p][d.x], 1);
    atomicAdd(&g_deg[p][d.y], 1);
    atomicAdd(&g_deg[p][d.z], 1);
    atomicAdd(&g_deg[p][d.w], 1);
}

// dinv + fused pcnt
__global__ void dinv_kernel(const int* __restrict__ batch, int p) {
    int i = blockIdx.x * blockDim.x + threadIdx.x;
    if (i < NN) {
        float d = (float)g_deg[p][i] + 1.0f;
        g_dinv[p][i]  = rsqrtf(d);
        g_dinv2[p][i] = 1.0f / d;
        atomicAdd(&g_pcnt[p][batch[i]], 1);
    }
}

// x fp32 -> fp16
__global__ void xcvt_kernel(const float* __restrict__ x, __half* __restrict__ xh) {
    size_t i = ((size_t)blockIdx.x * blockDim.x + threadIdx.x) * 4;
    if (i >= (size_t)NN * FIN) return;
    float4 v = *reinterpret_cast<const float4*>(x + i);
    *reinterpret_cast<uint2*>(xh + i) = pack_half4(v);
}

// W [K][256] fp32 -> WT [256][K] fp16
__global__ void wt_kernel(const float* __restrict__ W, __half* __restrict__ WT, int K) {
    int idx = blockIdx.x * blockDim.x + threadIdx.x;
    if (idx >= 256 * K) return;
    int n = idx / K, k = idx % K;
    WT[idx] = __float2half(W[(size_t)k * 256 + n]);
}

// ---------------- exclusive scan of deg -> rowptr ------------------------------
__global__ void scan1_kernel(int p) {
    __shared__ int s[1024];
    int t = threadIdx.x;
    int i = blockIdx.x * 1024 + t;
    int v = (i < NN) ? g_deg[p][i] : 0;
    int x = v;
    s[t] = x;
    __syncthreads();
#pragma unroll
    for (int off = 1; off < 1024; off <<= 1) {
        int y = (t >= off) ? s[t - off] : 0;
        __syncthreads();
        x += y;
        s[t] = x;
        __syncthreads();
    }
    if (i < NN) g_rowptr[p][i] = x - v;
    if (t == 1023) g_bsum[p][blockIdx.x] = x;
}

__global__ void scan2_kernel(int p) {
    __shared__ int s[128];
    int t = threadIdx.x;
    const int NB = (NN + 1023) >> 10;
    int v = (t < NB) ? g_bsum[p][t] : 0;
    int x = v;
    s[t] = x;
    __syncthreads();
#pragma unroll
    for (int off = 1; off < 128; off <<= 1) {
        int y = (t >= off) ? s[t - off] : 0;
        __syncthreads();
        x += y;
        s[t] = x;
        __syncthreads();
    }
    g_bsum2[p][t] = x - v;
}

__global__ void scan3_kernel(int p) {
    int i = blockIdx.x * blockDim.x + threadIdx.x;
    if (i < NN) g_rowptr[p][i] += g_bsum2[p][i >> 10];
    if (i == 0) g_rowptr[p][NN] = EE;
}

// 4 edges per thread
__global__ void csr_kernel(const int* __restrict__ src, const int* __restrict__ dst, int p) {
    int e4 = (blockIdx.x * blockDim.x + threadIdx.x) * 4;
    if (e4 >= EE) return;
    int4 s4 = *reinterpret_cast<const int4*>(src + e4);
    int4 d4 = *reinterpret_cast<const int4*>(dst + e4);
    int ss[4] = {s4.x, s4.y, s4.z, s4.w};
    int dd[4] = {d4.x, d4.y, d4.z, d4.w};
#pragma unroll
    for (int j = 0; j < 4; j++) {
        float coef = g_dinv[p][ss[j]] * g_dinv[p][dd[j]];
        int pos = g_rowptr[p][dd[j]] + atomicAdd(&g_off[p][dd[j]], 1);
        g_epack[p][pos] = make_int2(ss[j], __float_as_int(coef));
    }
}

// ---------------- layer-0 aggregation: agg = Â x (64-col halves, MLP=8) --------
__global__ void __launch_bounds__(256)
pullx_kernel(const __half* __restrict__ xh, __half* __restrict__ agg, int p)
{
    int n = (int)((blockIdx.x * (unsigned)blockDim.x + threadIdx.x) >> 5);
    int lane = threadIdx.x & 31;
    if (n >= NN) return;
    int c = blockIdx.y * 64 + lane * 2;

    float d2 = g_dinv2[p][n];
    float2 acc = make_float2(0.f, 0.f);
    {
        uint32_t sv = *reinterpret_cast<const uint32_t*>(xh + (size_t)n * FIN + c);
        hacc1(acc, d2, sv);
    }

    int e = g_rowptr[p][n];
    int end = g_rowptr[p][n + 1];
    const int2* ep = g_epack[p];

    for (; e + 7 < end; e += 8) {
        int2 pe[8];
        uint32_t v[8];
#pragma unroll
        for (int j = 0; j < 8; j++) pe[j] = ep[e + j];
#pragma unroll
        for (int j = 0; j < 8; j++)
            v[j] = *reinterpret_cast<const uint32_t*>(xh + (size_t)pe[j].x * FIN + c);
#pragma unroll
        for (int j = 0; j < 8; j++)
            hacc1(acc, __int_as_float(pe[j].y), v[j]);
    }
    for (; e < end; e++) {
        int2 pe = ep[e];
        uint32_t v = *reinterpret_cast<const uint32_t*>(xh + (size_t)pe.x * FIN + c);
        hacc1(acc, __int_as_float(pe.y), v);
    }

    __half2 h = __float22half2_rn(acc);
    *reinterpret_cast<uint32_t*>(agg + (size_t)n * FIN + c) = *reinterpret_cast<uint32_t*>(&h);
}

// ---------------- GEMM via HMMA: out = relu(A @ W + bias) (fp16 out) ----------
template <int K>
__global__ void __launch_bounds__(256, 2)
gemmh_kernel(const __half* __restrict__ A, const __half* __restrict__ WT,
             const float* __restrict__ bias, __half* __restrict__ Hout)
{
    __shared__ uint32_t As2[16 * 136];
    __shared__ uint32_t Bs2[16 * 136];

    const int t = threadIdx.x;
    const int lane = t & 31;
    const int wid = t >> 5;
    const int g = lane >> 2;
    const int q = lane & 3;
    const int wm = wid & 3;
    const int wn = wid >> 2;
    const int rowBase = blockIdx.x * 128;
    const int colBase = blockIdx.y * 128;

    const int sr = t >> 1;
    const int sh = t & 1;

    float acc[2][8][4];
#pragma unroll
    for (int mt = 0; mt < 2; mt++)
#pragma unroll
        for (int nt = 0; nt < 8; nt++)
#pragma unroll
            for (int i = 0; i < 4; i++) acc[mt][nt][i] = 0.f;

    const int arow = rowBase + sr;
    uint4 pa0, pa1, pb0, pb1;
    {
        pa0 = make_uint4(0u,0u,0u,0u); pa1 = pa0;
        if (arow < NN) {
            const __half* ap = A + (size_t)arow * K + sh * 16;
            pa0 = *reinterpret_cast<const uint4*>(ap);
            pa1 = *reinterpret_cast<const uint4*>(ap + 8);
        }
        const __half* bp = WT + (size_t)(colBase + sr) * K + sh * 16;
        pb0 = *reinterpret_cast<const uint4*>(bp);
        pb1 = *reinterpret_cast<const uint4*>(bp + 8);
    }

    for (int kb = 0; kb < K; kb += 32) {
        {
            uint32_t av[8] = {pa0.x, pa0.y, pa0.z, pa0.w, pa1.x, pa1.y, pa1.z, pa1.w};
            uint32_t bv[8] = {pb0.x, pb0.y, pb0.z, pb0.w, pb1.x, pb1.y, pb1.z, pb1.w};
            int kp0 = sh * 8;
#pragma unroll
            for (int j = 0; j < 8; j++) {
                As2[(kp0 + j) * 136 + sr] = av[j];
                Bs2[(kp0 + j) * 136 + sr] = bv[j];
            }
        }
        __syncthreads();

        if (kb + 32 < K) {
            int kn = kb + 32;
            pa0 = make_uint4(0u,0u,0u,0u); pa1 = pa0;
            if (arow < NN) {
                const __half* ap = A + (size_t)arow * K + kn + sh * 16;
                pa0 = *reinterpret_cast<const uint4*>(ap);
                pa1 = *reinterpret_cast<const uint4*>(ap + 8);
            }
            const __half* bp = WT + (size_t)(colBase + sr) * K + kn + sh * 16;
            pb0 = *reinterpret_cast<const uint4*>(bp);
            pb1 = *reinterpret_cast<const uint4*>(bp + 8);
        }

#pragma unroll
        for (int s = 0; s < 2; s++) {
            int kp = s * 8 + q;
            uint32_t afr[2][4];
#pragma unroll
            for (int mt = 0; mt < 2; mt++) {
                int R = wm * 32 + mt * 16;
                afr[mt][0] = As2[kp * 136 + R + g];
                afr[mt][1] = As2[kp * 136 + R + 8 + g];
                afr[mt][2] = As2[(kp + 4) * 136 + R + g];
                afr[mt][3] = As2[(kp + 4) * 136 + R + 8 + g];
            }
            uint32_t bfr[8][2];
#pragma unroll
            for (int nt = 0; nt < 8; nt++) {
                int nc = wn * 64 + nt * 8 + g;
                bfr[nt][0] = Bs2[kp * 136 + nc];
                bfr[nt][1] = Bs2[(kp + 4) * 136 + nc];
            }
#pragma unroll
            for (int mt = 0; mt < 2; mt++)
#pragma unroll
                for (int nt = 0; nt < 8; nt++)
                    mma16816(acc[mt][nt], afr[mt], bfr[nt]);
        }
        __syncthreads();
    }

#pragma unroll
    for (int mt = 0; mt < 2; mt++) {
        int row0 = rowBase + wm * 32 + mt * 16 + g;
        int row1 = row0 + 8;
#pragma unroll
        for (int nt = 0; nt < 8; nt++) {
            int col = colBase + wn * 64 + nt * 8 + q * 2;
            float2 bb = *reinterpret_cast<const float2*>(bias + col);
            if (row0 < NN) {
                float vx = fmaxf(acc[mt][nt][0] + bb.x, 0.f);
                float vy = fmaxf(acc[mt][nt][1] + bb.y, 0.f);
                __half2 h = __float22half2_rn(make_float2(vx, vy));
                *reinterpret_cast<uint32_t*>(Hout + (size_t)row0 * HH + col) =
                    *reinterpret_cast<uint32_t*>(&h);
            }
            if (row1 < NN) {
                float vx = fmaxf(acc[mt][nt][2] + bb.x, 0.f);
                float vy = fmaxf(acc[mt][nt][3] + bb.y, 0.f);
                __half2 h = __float22half2_rn(make_float2(vx, vy));
                *reinterpret_cast<uint32_t*>(Hout + (size_t)row1 * HH + col) =
                    *reinterpret_cast<uint32_t*>(&h);
            }
        }
    }
}

// ---------------- pull (column-half): agg = Â a  (a already relu'd) ------------
// blockIdx.y selects the 128-col half. doPool==1: pooled into psum only.
__global__ void __launch_bounds__(256)
pull_kernel(const __half* __restrict__ a, __half* __restrict__ agg,
            const int* __restrict__ batch, int doPool, int p)
{
    int n = (int)((blockIdx.x * (unsigned)blockDim.x + threadIdx.x) >> 5);
    int lane = threadIdx.x & 31;
    if (n >= NN) return;
    int c = blockIdx.y * 128 + lane * 4;

    float d2 = g_dinv2[p][n];
    float4 acc = make_float4(0.f, 0.f, 0.f, 0.f);
    {
        uint2 sv = *reinterpret_cast<const uint2*>(a + (size_t)n * HH + c);
        hacc2(acc, d2, sv);
    }

    int e = g_rowptr[p][n];
    int end = g_rowptr[p][n + 1];
    const int2* ep = g_epack[p];

    for (; e + 7 < end; e += 8) {
        int2 pe[8];
        uint2 v[8];
#pragma unroll
        for (int j = 0; j < 8; j++) pe[j] = ep[e + j];
#pragma unroll
        for (int j = 0; j < 8; j++)
            v[j] = *reinterpret_cast<const uint2*>(a + (size_t)pe[j].x * HH + c);
#pragma unroll
        for (int j = 0; j < 8; j++)
            hacc2(acc, __int_as_float(pe[j].y), v[j]);
    }
    for (; e < end; e++) {
        int2 pe = ep[e];
        uint2 v = *reinterpret_cast<const uint2*>(a + (size_t)pe.x * HH + c);
        hacc2(acc, __int_as_float(pe.y), v);
    }

    if (!doPool) {
        *reinterpret_cast<uint2*>(agg + (size_t)n * HH + c) = pack_half4(acc);
    } else {
        int g = __ldg(&batch[n]);
        red_add_v4(reinterpret_cast<float4*>(g_psum[p] + g * HH + c), acc);
    }
}

// ---------------- z: mean = psum/cnt ; t2 = mean@W2 + b2 ; z = t2@lin0W + lin0b -
__global__ void __launch_bounds__(256)
z_kernel(const float* __restrict__ W2, const float* __restrict__ b2,
         const float* __restrict__ lin0W, const float* __restrict__ lin0b,
         float* __restrict__ outz, int p)
{
    __shared__ float mean[HH];
    __shared__ float t2[HH];
    int g = blockIdx.x;
    int t = threadIdx.x;
    float cnt = fmaxf((float)g_pcnt[p][g], 1.0f);
    mean[t] = g_psum[p][g * HH + t] / cnt;
    __syncthreads();

    float acc = b2[t];
#pragma unroll 8
    for (int k = 0; k < HH; k++)
        acc = fmaf(mean[k], __ldg(&W2[(size_t)k * HH + t]), acc);
    t2[t] = acc;
    __syncthreads();

    if (t < HO) {
        float z = lin0b[t];
#pragma unroll 8
        for (int k = 0; k < HH; k++)
            z = fmaf(t2[k], __ldg(&lin0W[(size_t)k * HO + t]), z);
        outz[g * HO + t] = z;
    }
}

// ---------------- triplet head ------------------------------------------------
__global__ void final_kernel(const float* __restrict__ linW,
                             const float* __restrict__ linb,
                             float* __restrict__ out)
{
    __shared__ int s1, s2;
    int g = threadIdx.x;
    if (g == 0) { s1 = 0; s2 = 0; }
    __syncthreads();

    const float* z0 = out;
    const float* z1 = out + GG * HO;
    const float* z2 = out + 2 * GG * HO;
    const float EPS = 1e-6f;

    float dp = 0.f, dn = 0.f;
    float y1 = linb[0], y2 = linb[0];
#pragma unroll 4
    for (int j = 0; j < HO; j++) {
        float a = z0[g * HO + j];
        float b = z1[g * HO + j];
        float c = z2[g * HO + j];
        float e1 = a - b + EPS; dp = fmaf(e1, e1, dp);
        float e2 = a - c + EPS; dn = fmaf(e2, e2, dn);
        float wa = linW[j], wb = linW[HO + j];
        y1 = fmaf(a, wa, fmaf(b, wb, y1));
        y2 = fmaf(a, wa, fmaf(c, wb, y2));
    }
    dp = sqrtf(dp); dn = sqrtf(dn);
    float sp = 1.0f / (1.0f + expf(-y1));
    float sn = 1.0f / (1.0f + expf(-y2));

    const int base = 3 * GG * HO;
    out[base + 1 + g] = sp;
    out[base + 1 + GG + g] = sn;
    if (dn - dp > 0.f) atomicAdd(&s1, 1);
    if (sp - sn > 0.f) atomicAdd(&s2, 1);
    __syncthreads();
    if (g == 0) {
        out[base] = (float)s1;
        out[base + 1 + 2 * GG] = (float)s2;
    }
}

// ---------------- host orchestration ------------------------------------------
extern "C" void kernel_launch(void* const* d_in, const int* in_sizes, int n_in,
                              void* d_out, int out_size)
{
    const float* x[3]     = { (const float*)d_in[0], (const float*)d_in[1], (const float*)d_in[2] };
    const int*   ei[3]    = { (const int*)d_in[3], (const int*)d_in[4], (const int*)d_in[5] };
    const int*   batch[3] = { (const int*)d_in[6], (const int*)d_in[7], (const int*)d_in[8] };
    const float* W0 = (const float*)d_in[9];
    const float* b0 = (const float*)d_in[10];
    const float* W1 = (const float*)d_in[11];
    const float* b1 = (const float*)d_in[12];
    const float* W2 = (const float*)d_in[13];
    const float* b2 = (const float*)d_in[14];
    const float* lin0W = (const float*)d_in[15];
    const float* lin0b = (const float*)d_in[16];
    const float* linW  = (const float*)d_in[17];
    const float* linb  = (const float*)d_in[18];
    float* out = (float*)d_out;

    static cudaStream_t st[3];
    static cudaEvent_t evRoot, evDone[3];
    static bool inited = false;
    if (!inited) {
        for (int i = 0; i < 3; i++) cudaStreamCreateWithFlags(&st[i], cudaStreamNonBlocking);
        cudaEventCreateWithFlags(&evRoot, cudaEventDisableTiming);
        for (int i = 0; i < 3; i++) cudaEventCreateWithFlags(&evDone[i], cudaEventDisableTiming);
        inited = true;
    }

    __half *aptr[3], *aggptr[3], *xhptr[3], *wtbase;
    {
        __half* hb;
        cudaGetSymbolAddress((void**)&hb, g_a);
        for (int i = 0; i < 3; i++) aptr[i] = hb + (size_t)i * NH;
        cudaGetSymbolAddress((void**)&hb, g_agg);
        for (int i = 0; i < 3; i++) aggptr[i] = hb + (size_t)i * NH;
        cudaGetSymbolAddress((void**)&hb, g_xh);
        for (int i = 0; i < 3; i++) xhptr[i] = hb + (size_t)i * NN * FIN;
        cudaGetSymbolAddress((void**)&wtbase, g_wt);
    }
    __half* wt1 = wtbase;                 // [256][256]
    __half* wt0 = wtbase + 256 * HH;      // [256][128]

    dim3 gemmGrid((NN + 127) / 128, HH / 128);
    int  warpBlocks = (int)(((long long)NN * 32 + 255) / 256);
    dim3 pullGrid(warpBlocks, 2);
    dim3 pullxGrid(warpBlocks, 2);
    const int NB = (NN + 1023) / 1024;
    int  xcvtBlocks = (int)(((size_t)NN * FIN / 4 + 255) / 256);
    int  e4Blocks = (EE / 4 + 255) / 256;

    // weight transposes (shared by all passes) on the capture stream
    wt_kernel<<<(256 * HH + 255) / 256, 256>>>(W1, wt1, HH);
    wt_kernel<<<(256 * FIN + 255) / 256, 256>>>(W0, wt0, FIN);

    cudaEventRecord(evRoot, 0);

    for (int p = 0; p < 3; p++) {
        cudaStream_t s = st[p];
        cudaStreamWaitEvent(s, evRoot, 0);

        const int* srcp = ei[p];
        const int* dstp = ei[p] + EE;

        // ---- per-pass graph prep + x conversion ----
        zero_kernel<<<(NN + 255) / 256, 256, 0, s>>>(p);
        xcvt_kernel<<<xcvtBlocks, 256, 0, s>>>(x[p], xhptr[p]);
        deg_kernel<<<e4Blocks, 256, 0, s>>>(dstp, p);
        dinv_kernel<<<(NN + 255) / 256, 256, 0, s>>>(batch[p], p);
        scan1_kernel<<<NB, 1024, 0, s>>>(p);
        scan2_kernel<<<1, 128, 0, s>>>(p);
        scan3_kernel<<<(NN + 255) / 256, 256, 0, s>>>(p);
        csr_kernel<<<e4Blocks, 256, 0, s>>>(srcp, dstp, p);

        // ---- layer 0: agg0 = Â x (2 col halves) ; a = relu(agg0 @ W0 + b0)
        pullx_kernel<<<pullxGrid, 256, 0, s>>>(xhptr[p], aggptr[p], p);
        gemmh_kernel<FIN><<<gemmGrid, 256, 0, s>>>(aggptr[p], wt0, b0, aptr[p]);

        // ---- layer 1: agg1 = Â a (2 col halves) ; a = relu(agg1 @ W1 + b1)
        pull_kernel<<<pullGrid, 256, 0, s>>>(aptr[p], aggptr[p], nullptr, 0, p);
        gemmh_kernel<HH><<<gemmGrid, 256, 0, s>>>(aggptr[p], wt1, b1, aptr[p]);

        // ---- layer 2: psum = pool(Â a)  (2 col halves)
        pull_kernel<<<pullGrid, 256, 0, s>>>(aptr[p], nullptr, batch[p], 1, p);

        // ---- z = (psum/cnt @ W2 + b2) @ lin0W + lin0b
        z_kernel<<<GG, 256, 0, s>>>(W2, b2, lin0W, lin0b, out + (size_t)p * GG * HO, p);

        cudaEventRecord(evDone[p], s);
    }

    for (int p = 0; p < 3; p++) cudaStreamWaitEvent(0, evDone[p], 0);

    final_kernel<<<1, GG>>>(linW, linb, out);
}

// round 15
// speedup vs baseline: 1.0518x; 1.0518x over previous
#include <cuda_runtime.h>
#include <cuda_bf16.h>
#include <cuda_fp16.h>
#include <stdint.h>
#include <math.h>

// Problem constants (fixed by the dataset)
#define NN 100000
#define EE 3200000
#define FIN 128
#define HH  256
#define GG  64
#define HO  128   // H/2

typedef unsigned long long u64;

// ---------------- per-pass scratch (static device globals) --------------------
#define NH ((size_t)NN * HH)
__device__ __align__(16) __half g_a  [3][NH];                 // GEMM out (relu'd, gather source)
__device__ __align__(16) __half g_agg[3][NH];                 // pull out (GEMM A input)
__device__ __align__(16) __half g_xh [3][(size_t)NN * FIN];   // fp16 x
__device__ __align__(16) __half g_wt [256 * HH + 256 * FIN];  // fp16 WT: W1 [256][256], W0 [256][128]
__device__ float g_dinv [3][NN];
__device__ float g_dinv2[3][NN];
__device__ int   g_deg  [3][NN];
__device__ __align__(16) float g_psum[3][GG * HH];
__device__ int   g_pcnt[3][GG];
__device__ int   g_rowptr[3][NN + 1];
__device__ int   g_off[3][NN];
__device__ int   g_bsum[3][128];
__device__ int   g_bsum2[3][128];
__device__ __align__(16) int2 g_epack[3][EE];   // (src, coef-as-int)

// ---------------- helpers ----------------------------------------------------
__device__ __forceinline__ void red_add_v4(float4* addr, float4 v) {
    asm volatile("red.global.add.v4.f32 [%0], {%1,%2,%3,%4};"
                 :: "l"(addr), "f"(v.x), "f"(v.y), "f"(v.z), "f"(v.w)
                 : "memory");
}
__device__ __forceinline__ void hacc2(float4& a, float cf, uint2 v) {
    float2 x0 = __half22float2(*reinterpret_cast<const __half2*>(&v.x));
    float2 x1 = __half22float2(*reinterpret_cast<const __half2*>(&v.y));
    a.x = fmaf(cf, x0.x, a.x); a.y = fmaf(cf, x0.y, a.y);
    a.z = fmaf(cf, x1.x, a.z); a.w = fmaf(cf, x1.y, a.w);
}
__device__ __forceinline__ uint2 pack_half4(float4 v) {
    __half2 h0 = __float22half2_rn(make_float2(v.x, v.y));
    __half2 h1 = __float22half2_rn(make_float2(v.z, v.w));
    uint2 s;
    s.x = *reinterpret_cast<uint32_t*>(&h0);
    s.y = *reinterpret_cast<uint32_t*>(&h1);
    return s;
}
__device__ __forceinline__ float4 unpack_half4(uint2 s) {
    float2 a = __half22float2(*reinterpret_cast<const __half2*>(&s.x));
    float2 b = __half22float2(*reinterpret_cast<const __half2*>(&s.y));
    return make_float4(a.x, a.y, b.x, b.y);
}
__device__ __forceinline__ void mma16816(float* c, const uint32_t* a, const uint32_t* b) {
    asm volatile(
        "mma.sync.aligned.m16n8k16.row.col.f32.f16.f16.f32 "
        "{%0,%1,%2,%3}, {%4,%5,%6,%7}, {%8,%9}, {%0,%1,%2,%3};"
        : "+f"(c[0]), "+f"(c[1]), "+f"(c[2]), "+f"(c[3])
        : "r"(a[0]), "r"(a[1]), "r"(a[2]), "r"(a[3]), "r"(b[0]), "r"(b[1]));
}

// ---------------- per-pass setup ---------------------------------------------
__global__ void zero_kernel(int p) {
    int i = blockIdx.x * blockDim.x + threadIdx.x;
    if (i < NN)      { g_deg[p][i] = 0; g_off[p][i] = 0; }
    if (i < GG * HH) g_psum[p][i] = 0.f;
    if (i < GG)      g_pcnt[p][i] = 0;
}

// 4 edges per thread (EE % 4 == 0)
__global__ void deg_kernel(const int* __restrict__ dst, int p) {
    int e4 = (blockIdx.x * blockDim.x + threadIdx.x) * 4;
    if (e4 >= EE) return;
    int4 d = *reinterpret_cast<const int4*>(dst + e4);
    atomicAdd(&g_deg[p][d.x], 1);
    atomicAdd(&g_deg[p][d.y], 1);
    atomicAdd(&g_deg[p][d.z], 1);
    atomicAdd(&g_deg[p][d.w], 1);
}

// dinv + fused pcnt
__global__ void dinv_kernel(const int* __restrict__ batch, int p) {
    int i = blockIdx.x * blockDim.x + threadIdx.x;
    if (i < NN) {
        float d = (float)g_deg[p][i] + 1.0f;
        g_dinv[p][i]  = rsqrtf(d);
        g_dinv2[p][i] = 1.0f / d;
        atomicAdd(&g_pcnt[p][batch[i]], 1);
    }
}

// x fp32 -> fp16
__global__ void xcvt_kernel(const float* __restrict__ x, __half* __restrict__ xh) {
    size_t i = ((size_t)blockIdx.x * blockDim.x + threadIdx.x) * 4;
    if (i >= (size_t)NN * FIN) return;
    float4 v = *reinterpret_cast<const float4*>(x + i);
    *reinterpret_cast<uint2*>(xh + i) = pack_half4(v);
}

// W [K][256] fp32 -> WT [256][K] fp16
__global__ void wt_kernel(const float* __restrict__ W, __half* __restrict__ WT, int K) {
    int idx = blockIdx.x * blockDim.x + threadIdx.x;
    if (idx >= 256 * K) return;
    int n = idx / K, k = idx % K;
    WT[idx] = __float2half(W[(size_t)k * 256 + n]);
}

// ---------------- exclusive scan of deg -> rowptr ------------------------------
__global__ void scan1_kernel(int p) {
    __shared__ int s[1024];
    int t = threadIdx.x;
    int i = blockIdx.x * 1024 + t;
    int v = (i < NN) ? g_deg[p][i] : 0;
    int x = v;
    s[t] = x;
    __syncthreads();
#pragma unroll
    for (int off = 1; off < 1024; off <<= 1) {
        int y = (t >= off) ? s[t - off] : 0;
        __syncthreads();
        x += y;
        s[t] = x;
        __syncthreads();
    }
    if (i < NN) g_rowptr[p][i] = x - v;
    if (t == 1023) g_bsum[p][blockIdx.x] = x;
}

__global__ void scan2_kernel(int p) {
    __shared__ int s[128];
    int t = threadIdx.x;
    const int NB = (NN + 1023) >> 10;
    int v = (t < NB) ? g_bsum[p][t] : 0;
    int x = v;
    s[t] = x;
    __syncthreads();
#pragma unroll
    for (int off = 1; off < 128; off <<= 1) {
        int y = (t >= off) ? s[t - off] : 0;
        __syncthreads();
        x += y;
        s[t] = x;
        __syncthreads();
    }
    g_bsum2[p][t] = x - v;
}

__global__ void scan3_kernel(int p) {
    int i = blockIdx.x * blockDim.x + threadIdx.x;
    if (i < NN) g_rowptr[p][i] += g_bsum2[p][i >> 10];
    if (i == 0) g_rowptr[p][NN] = EE;
}

// 4 edges per thread
__global__ void csr_kernel(const int* __restrict__ src, const int* __restrict__ dst, int p) {
    int e4 = (blockIdx.x * blockDim.x + threadIdx.x) * 4;
    if (e4 >= EE) return;
    int4 s4 = *reinterpret_cast<const int4*>(src + e4);
    int4 d4 = *reinterpret_cast<const int4*>(dst + e4);
    int ss[4] = {s4.x, s4.y, s4.z, s4.w};
    int dd[4] = {d4.x, d4.y, d4.z, d4.w};
#pragma unroll
    for (int j = 0; j < 4; j++) {
        float coef = g_dinv[p][ss[j]] * g_dinv[p][dd[j]];
        int pos = g_rowptr[p][dd[j]] + atomicAdd(&g_off[p][dd[j]], 1);
        g_epack[p][pos] = make_int2(ss[j], __float_as_int(coef));
    }
}

// ---------------- layer-0 aggregation: agg = Â x (full 128 cols, MLP=8) --------
__global__ void __launch_bounds__(256)
pullx_kernel(const __half* __restrict__ xh, __half* __restrict__ agg, int p)
{
    int n = (int)((blockIdx.x * (unsigned)blockDim.x + threadIdx.x) >> 5);
    int lane = threadIdx.x & 31;
    if (n >= NN) return;
    int c = lane * 4;

    float d2 = g_dinv2[p][n];
    float4 acc = make_float4(0.f, 0.f, 0.f, 0.f);
    {
        uint2 sv = *reinterpret_cast<const uint2*>(xh + (size_t)n * FIN + c);
        hacc2(acc, d2, sv);
    }

    int e = g_rowptr[p][n];
    int end = g_rowptr[p][n + 1];
    const int2* ep = g_epack[p];

    for (; e + 7 < end; e += 8) {
        int2 pe[8];
        uint2 v[8];
#pragma unroll
        for (int j = 0; j < 8; j++) pe[j] = ep[e + j];
#pragma unroll
        for (int j = 0; j < 8; j++)
            v[j] = *reinterpret_cast<const uint2*>(xh + (size_t)pe[j].x * FIN + c);
#pragma unroll
        for (int j = 0; j < 8; j++)
            hacc2(acc, __int_as_float(pe[j].y), v[j]);
    }
    for (; e < end; e++) {
        int2 pe = ep[e];
        uint2 v = *reinterpret_cast<const uint2*>(xh + (size_t)pe.x * FIN + c);
        hacc2(acc, __int_as_float(pe.y), v);
    }

    *reinterpret_cast<uint2*>(agg + (size_t)n * FIN + c) = pack_half4(acc);
}

// ---------------- GEMM via HMMA: out = relu(A @ W + bias) (fp16 out) ----------
template <int K>
__global__ void __launch_bounds__(256, 2)
gemmh_kernel(const __half* __restrict__ A, const __half* __restrict__ WT,
             const float* __restrict__ bias, __half* __restrict__ Hout)
{
    __shared__ uint32_t As2[16 * 136];
    __shared__ uint32_t Bs2[16 * 136];

    const int t = threadIdx.x;
    const int lane = t & 31;
    const int wid = t >> 5;
    const int g = lane >> 2;
    const int q = lane & 3;
    const int wm = wid & 3;
    const int wn = wid >> 2;
    const int rowBase = blockIdx.x * 128;
    const int colBase = blockIdx.y * 128;

    const int sr = t >> 1;
    const int sh = t & 1;

    float acc[2][8][4];
#pragma unroll
    for (int mt = 0; mt < 2; mt++)
#pragma unroll
        for (int nt = 0; nt < 8; nt++)
#pragma unroll
            for (int i = 0; i < 4; i++) acc[mt][nt][i] = 0.f;

    const int arow = rowBase + sr;
    uint4 pa0, pa1, pb0, pb1;
    {
        pa0 = make_uint4(0u,0u,0u,0u); pa1 = pa0;
        if (arow < NN) {
            const __half* ap = A + (size_t)arow * K + sh * 16;
            pa0 = *reinterpret_cast<const uint4*>(ap);
            pa1 = *reinterpret_cast<const uint4*>(ap + 8);
        }
        const __half* bp = WT + (size_t)(colBase + sr) * K + sh * 16;
        pb0 = *reinterpret_cast<const uint4*>(bp);
        pb1 = *reinterpret_cast<const uint4*>(bp + 8);
    }

    for (int kb = 0; kb < K; kb += 32) {
        {
            uint32_t av[8] = {pa0.x, pa0.y, pa0.z, pa0.w, pa1.x, pa1.y, pa1.z, pa1.w};
            uint32_t bv[8] = {pb0.x, pb0.y, pb0.z, pb0.w, pb1.x, pb1.y, pb1.z, pb1.w};
            int kp0 = sh * 8;
#pragma unroll
            for (int j = 0; j < 8; j++) {
                As2[(kp0 + j) * 136 + sr] = av[j];
                Bs2[(kp0 + j) * 136 + sr] = bv[j];
            }
        }
        __syncthreads();

        if (kb + 32 < K) {
            int kn = kb + 32;
            pa0 = make_uint4(0u,0u,0u,0u); pa1 = pa0;
            if (arow < NN) {
                const __half* ap = A + (size_t)arow * K + kn + sh * 16;
                pa0 = *reinterpret_cast<const uint4*>(ap);
                pa1 = *reinterpret_cast<const uint4*>(ap + 8);
            }
            const __half* bp = WT + (size_t)(colBase + sr) * K + kn + sh * 16;
            pb0 = *reinterpret_cast<const uint4*>(bp);
            pb1 = *reinterpret_cast<const uint4*>(bp + 8);
        }

#pragma unroll
        for (int s = 0; s < 2; s++) {
            int kp = s * 8 + q;
            uint32_t afr[2][4];
#pragma unroll
            for (int mt = 0; mt < 2; mt++) {
                int R = wm * 32 + mt * 16;
                afr[mt][0] = As2[kp * 136 + R + g];
                afr[mt][1] = As2[kp * 136 + R + 8 + g];
                afr[mt][2] = As2[(kp + 4) * 136 + R + g];
                afr[mt][3] = As2[(kp + 4) * 136 + R + 8 + g];
            }
            uint32_t bfr[8][2];
#pragma unroll
            for (int nt = 0; nt < 8; nt++) {
                int nc = wn * 64 + nt * 8 + g;
                bfr[nt][0] = Bs2[kp * 136 + nc];
                bfr[nt][1] = Bs2[(kp + 4) * 136 + nc];
            }
#pragma unroll
            for (int mt = 0; mt < 2; mt++)
#pragma unroll
                for (int nt = 0; nt < 8; nt++)
                    mma16816(acc[mt][nt], afr[mt], bfr[nt]);
        }
        __syncthreads();
    }

#pragma unroll
    for (int mt = 0; mt < 2; mt++) {
        int row0 = rowBase + wm * 32 + mt * 16 + g;
        int row1 = row0 + 8;
#pragma unroll
        for (int nt = 0; nt < 8; nt++) {
            int col = colBase + wn * 64 + nt * 8 + q * 2;
            float2 bb = *reinterpret_cast<const float2*>(bias + col);
            if (row0 < NN) {
                float vx = fmaxf(acc[mt][nt][0] + bb.x, 0.f);
                float vy = fmaxf(acc[mt][nt][1] + bb.y, 0.f);
                __half2 h = __float22half2_rn(make_float2(vx, vy));
                *reinterpret_cast<uint32_t*>(Hout + (size_t)row0 * HH + col) =
                    *reinterpret_cast<uint32_t*>(&h);
            }
            if (row1 < NN) {
                float vx = fmaxf(acc[mt][nt][2] + bb.x, 0.f);
                float vy = fmaxf(acc[mt][nt][3] + bb.y, 0.f);
                __half2 h = __float22half2_rn(make_float2(vx, vy));
                *reinterpret_cast<uint32_t*>(Hout + (size_t)row1 * HH + col) =
                    *reinterpret_cast<uint32_t*>(&h);
            }
        }
    }
}

// ---------------- pull (column-half): agg = Â a  (a already relu'd) ------------
// blockIdx.y selects the 128-col half. doPool==1: pooled into psum only.
__global__ void __launch_bounds__(256)
pull_kernel(const __half* __restrict__ a, __half* __restrict__ agg,
            const int* __restrict__ batch, int doPool, int p)
{
    int n = (int)((blockIdx.x * (unsigned)blockDim.x + threadIdx.x) >> 5);
    int lane = threadIdx.x & 31;
    if (n >= NN) return;
    int c = blockIdx.y * 128 + lane * 4;

    float d2 = g_dinv2[p][n];
    float4 acc = make_float4(0.f, 0.f, 0.f, 0.f);
    {
        uint2 sv = *reinterpret_cast<const uint2*>(a + (size_t)n * HH + c);
        hacc2(acc, d2, sv);
    }

    int e = g_rowptr[p][n];
    int end = g_rowptr[p][n + 1];
    const int2* ep = g_epack[p];

    for (; e + 7 < end; e += 8) {
        int2 pe[8];
        uint2 v[8];
#pragma unroll
        for (int j = 0; j < 8; j++) pe[j] = ep[e + j];
#pragma unroll
        for (int j = 0; j < 8; j++)
            v[j] = *reinterpret_cast<const uint2*>(a + (size_t)pe[j].x * HH + c);
#pragma unroll
        for (int j = 0; j < 8; j++)
            hacc2(acc, __int_as_float(pe[j].y), v[j]);
    }
    for (; e < end; e++) {
        int2 pe = ep[e];
        uint2 v = *reinterpret_cast<const uint2*>(a + (size_t)pe.x * HH + c);
        hacc2(acc, __int_as_float(pe.y), v);
    }

    if (!doPool) {
        *reinterpret_cast<uint2*>(agg + (size_t)n * HH + c) = pack_half4(acc);
    } else {
        int g = __ldg(&batch[n]);
        red_add_v4(reinterpret_cast<float4*>(g_psum[p] + g * HH + c), acc);
    }
}

// ---------------- z: mean = psum/cnt ; t2 = mean@W2 + b2 ; z = t2@lin0W + lin0b -
__global__ void __launch_bounds__(256)
z_kernel(const float* __restrict__ W2, const float* __restrict__ b2,
         const float* __restrict__ lin0W, const float* __restrict__ lin0b,
         float* __restrict__ outz, int p)
{
    __shared__ float mean[HH];
    __shared__ float t2[HH];
    int g = blockIdx.x;
    int t = threadIdx.x;
    float cnt = fmaxf((float)g_pcnt[p][g], 1.0f);
    mean[t] = g_psum[p][g * HH + t] / cnt;
    __syncthreads();

    float acc = b2[t];
#pragma unroll 8
    for (int k = 0; k < HH; k++)
        acc = fmaf(mean[k], __ldg(&W2[(size_t)k * HH + t]), acc);
    t2[t] = acc;
    __syncthreads();

    if (t < HO) {
        float z = lin0b[t];
#pragma unroll 8
        for (int k = 0; k < HH; k++)
            z = fmaf(t2[k], __ldg(&lin0W[(size_t)k * HO + t]), z);
        outz[g * HO + t] = z;
    }
}

// ---------------- triplet head ------------------------------------------------
__global__ void final_kernel(const float* __restrict__ linW,
                             const float* __restrict__ linb,
                             float* __restrict__ out)
{
    __shared__ int s1, s2;
    int g = threadIdx.x;
    if (g == 0) { s1 = 0; s2 = 0; }
    __syncthreads();

    const float* z0 = out;
    const float* z1 = out + GG * HO;
    const float* z2 = out + 2 * GG * HO;
    const float EPS = 1e-6f;

    float dp = 0.f, dn = 0.f;
    float y1 = linb[0], y2 = linb[0];
#pragma unroll 4
    for (int j = 0; j < HO; j++) {
        float a = z0[g * HO + j];
        float b = z1[g * HO + j];
        float c = z2[g * HO + j];
        float e1 = a - b + EPS; dp = fmaf(e1, e1, dp);
        float e2 = a - c + EPS; dn = fmaf(e2, e2, dn);
        float wa = linW[j], wb = linW[HO + j];
        y1 = fmaf(a, wa, fmaf(b, wb, y1));
        y2 = fmaf(a, wa, fmaf(c, wb, y2));
    }
    dp = sqrtf(dp); dn = sqrtf(dn);
    float sp = 1.0f / (1.0f + expf(-y1));
    float sn = 1.0f / (1.0f + expf(-y2));

    const int base = 3 * GG * HO;
    out[base + 1 + g] = sp;
    out[base + 1 + GG + g] = sn;
    if (dn - dp > 0.f) atomicAdd(&s1, 1);
    if (sp - sn > 0.f) atomicAdd(&s2, 1);
    __syncthreads();
    if (g == 0) {
        out[base] = (float)s1;
        out[base + 1 + 2 * GG] = (float)s2;
    }
}

// ---------------- host orchestration ------------------------------------------
extern "C" void kernel_launch(void* const* d_in, const int* in_sizes, int n_in,
                              void* d_out, int out_size)
{
    const float* x[3]     = { (const float*)d_in[0], (const float*)d_in[1], (const float*)d_in[2] };
    const int*   ei[3]    = { (const int*)d_in[3], (const int*)d_in[4], (const int*)d_in[5] };
    const int*   batch[3] = { (const int*)d_in[6], (const int*)d_in[7], (const int*)d_in[8] };
    const float* W0 = (const float*)d_in[9];
    const float* b0 = (const float*)d_in[10];
    const float* W1 = (const float*)d_in[11];
    const float* b1 = (const float*)d_in[12];
    const float* W2 = (const float*)d_in[13];
    const float* b2 = (const float*)d_in[14];
    const float* lin0W = (const float*)d_in[15];
    const float* lin0b = (const float*)d_in[16];
    const float* linW  = (const float*)d_in[17];
    const float* linb  = (const float*)d_in[18];
    float* out = (float*)d_out;

    static cudaStream_t st[3];
    static cudaEvent_t evRoot, evDone[3];
    static bool inited = false;
    if (!inited) {
        for (int i = 0; i < 3; i++) cudaStreamCreateWithFlags(&st[i], cudaStreamNonBlocking);
        cudaEventCreateWithFlags(&evRoot, cudaEventDisableTiming);
        for (int i = 0; i < 3; i++) cudaEventCreateWithFlags(&evDone[i], cudaEventDisableTiming);
        inited = true;
    }

    __half *aptr[3], *aggptr[3], *xhptr[3], *wtbase;
    {
        __half* hb;
        cudaGetSymbolAddress((void**)&hb, g_a);
        for (int i = 0; i < 3; i++) aptr[i] = hb + (size_t)i * NH;
        cudaGetSymbolAddress((void**)&hb, g_agg);
        for (int i = 0; i < 3; i++) aggptr[i] = hb + (size_t)i * NH;
        cudaGetSymbolAddress((void**)&hb, g_xh);
        for (int i = 0; i < 3; i++) xhptr[i] = hb + (size_t)i * NN * FIN;
        cudaGetSymbolAddress((void**)&wtbase, g_wt);
    }
    __half* wt1 = wtbase;                 // [256][256]
    __half* wt0 = wtbase + 256 * HH;      // [256][128]

    dim3 gemmGrid((NN + 127) / 128, HH / 128);
    int  warpBlocks = (int)(((long long)NN * 32 + 255) / 256);
    dim3 pullGrid(warpBlocks, 2);
    const int NB = (NN + 1023) / 1024;
    int  xcvtBlocks = (int)(((size_t)NN * FIN / 4 + 255) / 256);
    int  e4Blocks = (EE / 4 + 255) / 256;

    // weight transposes (shared by all passes) on the capture stream
    wt_kernel<<<(256 * HH + 255) / 256, 256>>>(W1, wt1, HH);
    wt_kernel<<<(256 * FIN + 255) / 256, 256>>>(W0, wt0, FIN);

    cudaEventRecord(evRoot, 0);

    for (int p = 0; p < 3; p++) {
        cudaStream_t s = st[p];
        cudaStreamWaitEvent(s, evRoot, 0);

        const int* srcp = ei[p];
        const int* dstp = ei[p] + EE;

        // ---- per-pass graph prep + x conversion ----
        zero_kernel<<<(NN + 255) / 256, 256, 0, s>>>(p);
        xcvt_kernel<<<xcvtBlocks, 256, 0, s>>>(x[p], xhptr[p]);
        deg_kernel<<<e4Blocks, 256, 0, s>>>(dstp, p);
        dinv_kernel<<<(NN + 255) / 256, 256, 0, s>>>(batch[p], p);
        scan1_kernel<<<NB, 1024, 0, s>>>(p);
        scan2_kernel<<<1, 128, 0, s>>>(p);
        scan3_kernel<<<(NN + 255) / 256, 256, 0, s>>>(p);
        csr_kernel<<<e4Blocks, 256, 0, s>>>(srcp, dstp, p);

        // ---- layer 0: agg0 = Â x (full 128 cols) ; a = relu(agg0 @ W0 + b0)
        pullx_kernel<<<warpBlocks, 256, 0, s>>>(xhptr[p], aggptr[p], p);
        gemmh_kernel<FIN><<<gemmGrid, 256, 0, s>>>(aggptr[p], wt0, b0, aptr[p]);

        // ---- layer 1: agg1 = Â a (2 col halves) ; a = relu(agg1 @ W1 + b1)
        pull_kernel<<<pullGrid, 256, 0, s>>>(aptr[p], aggptr[p], nullptr, 0, p);
        gemmh_kernel<HH><<<gemmGrid, 256, 0, s>>>(aggptr[p], wt1, b1, aptr[p]);

        // ---- layer 2: psum = pool(Â a)  (2 col halves)
        pull_kernel<<<pullGrid, 256, 0, s>>>(aptr[p], nullptr, batch[p], 1, p);

        // ---- z = (psum/cnt @ W2 + b2) @ lin0W + lin0b
        z_kernel<<<GG, 256, 0, s>>>(W2, b2, lin0W, lin0b, out + (size_t)p * GG * HO, p);

        cudaEventRecord(evDone[p], s);
    }

    for (int p = 0; p < 3; p++) cudaStreamWaitEvent(0, evDone[p], 0);

    final_kernel<<<1, GG>>>(linW, linb, out);
}

// round 16
// speedup vs baseline: 1.0527x; 1.0009x over previous
#include <cuda_runtime.h>
#include <cuda_bf16.h>
#include <cuda_fp16.h>
#include <stdint.h>
#include <math.h>

// Problem constants (fixed by the dataset)
#define NN 100000
#define EE 3200000
#define FIN 128
#define HH  256
#define GG  64
#define HO  128   // H/2

typedef unsigned long long u64;

// ---------------- per-pass scratch (static device globals) --------------------
#define NH ((size_t)NN * HH)
__device__ __align__(16) __half g_a  [3][NH];                 // GEMM out (relu'd, gather source)
__device__ __align__(16) __half g_agg[3][NH];                 // pull out (GEMM A input)
__device__ __align__(16) __half g_xh [3][(size_t)NN * FIN];   // fp16 x
__device__ __align__(16) __half g_wt [256 * HH + 256 * FIN];  // fp16 WT: W1 [256][256], W0 [256][128]
__device__ float g_dinv [3][NN];
__device__ float g_dinv2[3][NN];
__device__ int   g_deg  [3][NN];
__device__ __align__(16) float g_psum[3][GG * HH];
__device__ int   g_pcnt[3][GG];
__device__ int   g_rowptr[3][NN + 1];
__device__ int   g_off[3][NN];
__device__ int   g_bsum[3][128];
__device__ int   g_bsum2[3][128];
__device__ __align__(16) int2 g_epack[3][EE];   // (src, coef-as-int)

// ---------------- helpers ----------------------------------------------------
__device__ __forceinline__ void red_add_v4(float4* addr, float4 v) {
    asm volatile("red.global.add.v4.f32 [%0], {%1,%2,%3,%4};"
                 :: "l"(addr), "f"(v.x), "f"(v.y), "f"(v.z), "f"(v.w)
                 : "memory");
}
__device__ __forceinline__ void hacc2(float4& a, float cf, uint2 v) {
    float2 x0 = __half22float2(*reinterpret_cast<const __half2*>(&v.x));
    float2 x1 = __half22float2(*reinterpret_cast<const __half2*>(&v.y));
    a.x = fmaf(cf, x0.x, a.x); a.y = fmaf(cf, x0.y, a.y);
    a.z = fmaf(cf, x1.x, a.z); a.w = fmaf(cf, x1.y, a.w);
}
__device__ __forceinline__ uint2 pack_half4(float4 v) {
    __half2 h0 = __float22half2_rn(make_float2(v.x, v.y));
    __half2 h1 = __float22half2_rn(make_float2(v.z, v.w));
    uint2 s;
    s.x = *reinterpret_cast<uint32_t*>(&h0);
    s.y = *reinterpret_cast<uint32_t*>(&h1);
    return s;
}
__device__ __forceinline__ void mma16816(float* c, const uint32_t* a, const uint32_t* b) {
    asm volatile(
        "mma.sync.aligned.m16n8k16.row.col.f32.f16.f16.f32 "
        "{%0,%1,%2,%3}, {%4,%5,%6,%7}, {%8,%9}, {%0,%1,%2,%3};"
        : "+f"(c[0]), "+f"(c[1]), "+f"(c[2]), "+f"(c[3])
        : "r"(a[0]), "r"(a[1]), "r"(a[2]), "r"(a[3]), "r"(b[0]), "r"(b[1]));
}

// ---------------- per-pass setup ---------------------------------------------
__global__ void zero_kernel(int p) {
    int i = blockIdx.x * blockDim.x + threadIdx.x;
    if (i < NN)      g_deg[p][i] = 0;
    if (i < GG * HH) g_psum[p][i] = 0.f;
    if (i < GG)      g_pcnt[p][i] = 0;
}

// 4 edges per thread (EE % 4 == 0)
__global__ void deg_kernel(const int* __restrict__ dst, int p) {
    int e4 = (blockIdx.x * blockDim.x + threadIdx.x) * 4;
    if (e4 >= EE) return;
    int4 d = *reinterpret_cast<const int4*>(dst + e4);
    atomicAdd(&g_deg[p][d.x], 1);
    atomicAdd(&g_deg[p][d.y], 1);
    atomicAdd(&g_deg[p][d.z], 1);
    atomicAdd(&g_deg[p][d.w], 1);
}

// dinv + fused pcnt
__global__ void dinv_kernel(const int* __restrict__ batch, int p) {
    int i = blockIdx.x * blockDim.x + threadIdx.x;
    if (i < NN) {
        float d = (float)g_deg[p][i] + 1.0f;
        g_dinv[p][i]  = rsqrtf(d);
        g_dinv2[p][i] = 1.0f / d;
        atomicAdd(&g_pcnt[p][batch[i]], 1);
    }
}

// x fp32 -> fp16
__global__ void xcvt_kernel(const float* __restrict__ x, __half* __restrict__ xh) {
    size_t i = ((size_t)blockIdx.x * blockDim.x + threadIdx.x) * 4;
    if (i >= (size_t)NN * FIN) return;
    float4 v = *reinterpret_cast<const float4*>(x + i);
    *reinterpret_cast<uint2*>(xh + i) = pack_half4(v);
}

// W [K][256] fp32 -> WT [256][K] fp16
__global__ void wt_kernel(const float* __restrict__ W, __half* __restrict__ WT, int K) {
    int idx = blockIdx.x * blockDim.x + threadIdx.x;
    if (idx >= 256 * K) return;
    int n = idx / K, k = idx % K;
    WT[idx] = __float2half(W[(size_t)k * 256 + n]);
}

// ---------------- exclusive scan of deg -> rowptr ------------------------------
__global__ void scan1_kernel(int p) {
    __shared__ int s[1024];
    int t = threadIdx.x;
    int i = blockIdx.x * 1024 + t;
    int v = (i < NN) ? g_deg[p][i] : 0;
    int x = v;
    s[t] = x;
    __syncthreads();
#pragma unroll
    for (int off = 1; off < 1024; off <<= 1) {
        int y = (t >= off) ? s[t - off] : 0;
        __syncthreads();
        x += y;
        s[t] = x;
        __syncthreads();
    }
    if (i < NN) g_rowptr[p][i] = x - v;
    if (t == 1023) g_bsum[p][blockIdx.x] = x;
}

__global__ void scan2_kernel(int p) {
    __shared__ int s[128];
    int t = threadIdx.x;
    const int NB = (NN + 1023) >> 10;
    int v = (t < NB) ? g_bsum[p][t] : 0;
    int x = v;
    s[t] = x;
    __syncthreads();
#pragma unroll
    for (int off = 1; off < 128; off <<= 1) {
        int y = (t >= off) ? s[t - off] : 0;
        __syncthreads();
        x += y;
        s[t] = x;
        __syncthreads();
    }
    g_bsum2[p][t] = x - v;
}

// rowptr finalize + seed g_off with the start offsets (csr then needs ONE atomic)
__global__ void scan3_kernel(int p) {
    int i = blockIdx.x * blockDim.x + threadIdx.x;
    if (i < NN) {
        int rp = g_rowptr[p][i] + g_bsum2[p][i >> 10];
        g_rowptr[p][i] = rp;
        g_off[p][i] = rp;
    }
    if (i == 0) g_rowptr[p][NN] = EE;
}

// 4 edges per thread; position directly from atomicAdd on pre-seeded g_off
__global__ void csr_kernel(const int* __restrict__ src, const int* __restrict__ dst, int p) {
    int e4 = (blockIdx.x * blockDim.x + threadIdx.x) * 4;
    if (e4 >= EE) return;
    int4 s4 = *reinterpret_cast<const int4*>(src + e4);
    int4 d4 = *reinterpret_cast<const int4*>(dst + e4);
    int ss[4] = {s4.x, s4.y, s4.z, s4.w};
    int dd[4] = {d4.x, d4.y, d4.z, d4.w};
#pragma unroll
    for (int j = 0; j < 4; j++) {
        float coef = g_dinv[p][ss[j]] * g_dinv[p][dd[j]];
        int pos = atomicAdd(&g_off[p][dd[j]], 1);
        g_epack[p][pos] = make_int2(ss[j], __float_as_int(coef));
    }
}

// ---------------- layer-0 aggregation: agg = Â x (full 128 cols, MLP=8) --------
__global__ void __launch_bounds__(256)
pullx_kernel(const __half* __restrict__ xh, __half* __restrict__ agg, int p)
{
    int n = (int)((blockIdx.x * (unsigned)blockDim.x + threadIdx.x) >> 5);
    int lane = threadIdx.x & 31;
    if (n >= NN) return;
    int c = lane * 4;

    float d2 = g_dinv2[p][n];
    float4 acc = make_float4(0.f, 0.f, 0.f, 0.f);
    {
        uint2 sv = *reinterpret_cast<const uint2*>(xh + (size_t)n * FIN + c);
        hacc2(acc, d2, sv);
    }

    int e = g_rowptr[p][n];
    int end = g_rowptr[p][n + 1];
    const int2* ep = g_epack[p];

    // peel to even index so int4 paired loads are 16B-aligned
    if ((e & 1) && e < end) {
        int2 pe = ep[e];
        uint2 v = *reinterpret_cast<const uint2*>(xh + (size_t)pe.x * FIN + c);
        hacc2(acc, __int_as_float(pe.y), v);
        e++;
    }
    for (; e + 7 < end; e += 8) {
        int4 q0 = *reinterpret_cast<const int4*>(&ep[e + 0]);
        int4 q1 = *reinterpret_cast<const int4*>(&ep[e + 2]);
        int4 q2 = *reinterpret_cast<const int4*>(&ep[e + 4]);
        int4 q3 = *reinterpret_cast<const int4*>(&ep[e + 6]);
        uint2 v[8];
        v[0] = *reinterpret_cast<const uint2*>(xh + (size_t)q0.x * FIN + c);
        v[1] = *reinterpret_cast<const uint2*>(xh + (size_t)q0.z * FIN + c);
        v[2] = *reinterpret_cast<const uint2*>(xh + (size_t)q1.x * FIN + c);
        v[3] = *reinterpret_cast<const uint2*>(xh + (size_t)q1.z * FIN + c);
        v[4] = *reinterpret_cast<const uint2*>(xh + (size_t)q2.x * FIN + c);
        v[5] = *reinterpret_cast<const uint2*>(xh + (size_t)q2.z * FIN + c);
        v[6] = *reinterpret_cast<const uint2*>(xh + (size_t)q3.x * FIN + c);
        v[7] = *reinterpret_cast<const uint2*>(xh + (size_t)q3.z * FIN + c);
        hacc2(acc, __int_as_float(q0.y), v[0]);
        hacc2(acc, __int_as_float(q0.w), v[1]);
        hacc2(acc, __int_as_float(q1.y), v[2]);
        hacc2(acc, __int_as_float(q1.w), v[3]);
        hacc2(acc, __int_as_float(q2.y), v[4]);
        hacc2(acc, __int_as_float(q2.w), v[5]);
        hacc2(acc, __int_as_float(q3.y), v[6]);
        hacc2(acc, __int_as_float(q3.w), v[7]);
    }
    for (; e < end; e++) {
        int2 pe = ep[e];
        uint2 v = *reinterpret_cast<const uint2*>(xh + (size_t)pe.x * FIN + c);
        hacc2(acc, __int_as_float(pe.y), v);
    }

    *reinterpret_cast<uint2*>(agg + (size_t)n * FIN + c) = pack_half4(acc);
}

// ---------------- GEMM via HMMA: out = relu(A @ W + bias) (fp16 out) ----------
template <int K>
__global__ void __launch_bounds__(256, 2)
gemmh_kernel(const __half* __restrict__ A, const __half* __restrict__ WT,
             const float* __restrict__ bias, __half* __restrict__ Hout)
{
    __shared__ uint32_t As2[16 * 136];
    __shared__ uint32_t Bs2[16 * 136];

    const int t = threadIdx.x;
    const int lane = t & 31;
    const int wid = t >> 5;
    const int g = lane >> 2;
    const int q = lane & 3;
    const int wm = wid & 3;
    const int wn = wid >> 2;
    const int rowBase = blockIdx.x * 128;
    const int colBase = blockIdx.y * 128;

    const int sr = t >> 1;
    const int sh = t & 1;

    float acc[2][8][4];
#pragma unroll
    for (int mt = 0; mt < 2; mt++)
#pragma unroll
        for (int nt = 0; nt < 8; nt++)
#pragma unroll
            for (int i = 0; i < 4; i++) acc[mt][nt][i] = 0.f;

    const int arow = rowBase + sr;
    uint4 pa0, pa1, pb0, pb1;
    {
        pa0 = make_uint4(0u,0u,0u,0u); pa1 = pa0;
        if (arow < NN) {
            const __half* ap = A + (size_t)arow * K + sh * 16;
            pa0 = *reinterpret_cast<const uint4*>(ap);
            pa1 = *reinterpret_cast<const uint4*>(ap + 8);
        }
        const __half* bp = WT + (size_t)(colBase + sr) * K + sh * 16;
        pb0 = *reinterpret_cast<const uint4*>(bp);
        pb1 = *reinterpret_cast<const uint4*>(bp + 8);
    }

    for (int kb = 0; kb < K; kb += 32) {
        {
            uint32_t av[8] = {pa0.x, pa0.y, pa0.z, pa0.w, pa1.x, pa1.y, pa1.z, pa1.w};
            uint32_t bv[8] = {pb0.x, pb0.y, pb0.z, pb0.w, pb1.x, pb1.y, pb1.z, pb1.w};
            int kp0 = sh * 8;
#pragma unroll
            for (int j = 0; j < 8; j++) {
                As2[(kp0 + j) * 136 + sr] = av[j];
                Bs2[(kp0 + j) * 136 + sr] = bv[j];
            }
        }
        __syncthreads();

        if (kb + 32 < K) {
            int kn = kb + 32;
            pa0 = make_uint4(0u,0u,0u,0u); pa1 = pa0;
            if (arow < NN) {
                const __half* ap = A + (size_t)arow * K + kn + sh * 16;
                pa0 = *reinterpret_cast<const uint4*>(ap);
                pa1 = *reinterpret_cast<const uint4*>(ap + 8);
            }
            const __half* bp = WT + (size_t)(colBase + sr) * K + kn + sh * 16;
            pb0 = *reinterpret_cast<const uint4*>(bp);
            pb1 = *reinterpret_cast<const uint4*>(bp + 8);
        }

#pragma unroll
        for (int s = 0; s < 2; s++) {
            int kp = s * 8 + q;
            uint32_t afr[2][4];
#pragma unroll
            for (int mt = 0; mt < 2; mt++) {
                int R = wm * 32 + mt * 16;
                afr[mt][0] = As2[kp * 136 + R + g];
                afr[mt][1] = As2[kp * 136 + R + 8 + g];
                afr[mt][2] = As2[(kp + 4) * 136 + R + g];
                afr[mt][3] = As2[(kp + 4) * 136 + R + 8 + g];
            }
            uint32_t bfr[8][2];
#pragma unroll
            for (int nt = 0; nt < 8; nt++) {
                int nc = wn * 64 + nt * 8 + g;
                bfr[nt][0] = Bs2[kp * 136 + nc];
                bfr[nt][1] = Bs2[(kp + 4) * 136 + nc];
            }
#pragma unroll
            for (int mt = 0; mt < 2; mt++)
#pragma unroll
                for (int nt = 0; nt < 8; nt++)
                    mma16816(acc[mt][nt], afr[mt], bfr[nt]);
        }
        __syncthreads();
    }

#pragma unroll
    for (int mt = 0; mt < 2; mt++) {
        int row0 = rowBase + wm * 32 + mt * 16 + g;
        int row1 = row0 + 8;
#pragma unroll
        for (int nt = 0; nt < 8; nt++) {
            int col = colBase + wn * 64 + nt * 8 + q * 2;
            float2 bb = *reinterpret_cast<const float2*>(bias + col);
            if (row0 < NN) {
                float vx = fmaxf(acc[mt][nt][0] + bb.x, 0.f);
                float vy = fmaxf(acc[mt][nt][1] + bb.y, 0.f);
                __half2 h = __float22half2_rn(make_float2(vx, vy));
                *reinterpret_cast<uint32_t*>(Hout + (size_t)row0 * HH + col) =
                    *reinterpret_cast<uint32_t*>(&h);
            }
            if (row1 < NN) {
                float vx = fmaxf(acc[mt][nt][2] + bb.x, 0.f);
                float vy = fmaxf(acc[mt][nt][3] + bb.y, 0.f);
                __half2 h = __float22half2_rn(make_float2(vx, vy));
                *reinterpret_cast<uint32_t*>(Hout + (size_t)row1 * HH + col) =
                    *reinterpret_cast<uint32_t*>(&h);
            }
        }
    }
}

// ---------------- pull (column-half): agg = Â a  (a already relu'd) ------------
// blockIdx.y selects the 128-col half. doPool==1: pooled into psum only.
__global__ void __launch_bounds__(256)
pull_kernel(const __half* __restrict__ a, __half* __restrict__ agg,
            const int* __restrict__ batch, int doPool, int p)
{
    int n = (int)((blockIdx.x * (unsigned)blockDim.x + threadIdx.x) >> 5);
    int lane = threadIdx.x & 31;
    if (n >= NN) return;
    int c = blockIdx.y * 128 + lane * 4;

    float d2 = g_dinv2[p][n];
    float4 acc = make_float4(0.f, 0.f, 0.f, 0.f);
    {
        uint2 sv = *reinterpret_cast<const uint2*>(a + (size_t)n * HH + c);
        hacc2(acc, d2, sv);
    }

    int e = g_rowptr[p][n];
    int end = g_rowptr[p][n + 1];
    const int2* ep = g_epack[p];

    if ((e & 1) && e < end) {
        int2 pe = ep[e];
        uint2 v = *reinterpret_cast<const uint2*>(a + (size_t)pe.x * HH + c);
        hacc2(acc, __int_as_float(pe.y), v);
        e++;
    }
    for (; e + 7 < end; e += 8) {
        int4 q0 = *reinterpret_cast<const int4*>(&ep[e + 0]);
        int4 q1 = *reinterpret_cast<const int4*>(&ep[e + 2]);
        int4 q2 = *reinterpret_cast<const int4*>(&ep[e + 4]);
        int4 q3 = *reinterpret_cast<const int4*>(&ep[e + 6]);
        uint2 v[8];
        v[0] = *reinterpret_cast<const uint2*>(a + (size_t)q0.x * HH + c);
        v[1] = *reinterpret_cast<const uint2*>(a + (size_t)q0.z * HH + c);
        v[2] = *reinterpret_cast<const uint2*>(a + (size_t)q1.x * HH + c);
        v[3] = *reinterpret_cast<const uint2*>(a + (size_t)q1.z * HH + c);
        v[4] = *reinterpret_cast<const uint2*>(a + (size_t)q2.x * HH + c);
        v[5] = *reinterpret_cast<const uint2*>(a + (size_t)q2.z * HH + c);
        v[6] = *reinterpret_cast<const uint2*>(a + (size_t)q3.x * HH + c);
        v[7] = *reinterpret_cast<const uint2*>(a + (size_t)q3.z * HH + c);
        hacc2(acc, __int_as_float(q0.y), v[0]);
        hacc2(acc, __int_as_float(q0.w), v[1]);
        hacc2(acc, __int_as_float(q1.y), v[2]);
        hacc2(acc, __int_as_float(q1.w), v[3]);
        hacc2(acc, __int_as_float(q2.y), v[4]);
        hacc2(acc, __int_as_float(q2.w), v[5]);
        hacc2(acc, __int_as_float(q3.y), v[6]);
        hacc2(acc, __int_as_float(q3.w), v[7]);
    }
    for (; e < end; e++) {
        int2 pe = ep[e];
        uint2 v = *reinterpret_cast<const uint2*>(a + (size_t)pe.x * HH + c);
        hacc2(acc, __int_as_float(pe.y), v);
    }

    if (!doPool) {
        *reinterpret_cast<uint2*>(agg + (size_t)n * HH + c) = pack_half4(acc);
    } else {
        int g = __ldg(&batch[n]);
        red_add_v4(reinterpret_cast<float4*>(g_psum[p] + g * HH + c), acc);
    }
}

// ---------------- z: mean = psum/cnt ; t2 = mean@W2 + b2 ; z = t2@lin0W + lin0b -
__global__ void __launch_bounds__(256)
z_kernel(const float* __restrict__ W2, const float* __restrict__ b2,
         const float* __restrict__ lin0W, const float* __restrict__ lin0b,
         float* __restrict__ outz, int p)
{
    __shared__ float mean[HH];
    __shared__ float t2[HH];
    int g = blockIdx.x;
    int t = threadIdx.x;
    float cnt = fmaxf((float)g_pcnt[p][g], 1.0f);
    mean[t] = g_psum[p][g * HH + t] / cnt;
    __syncthreads();

    float acc = b2[t];
#pragma unroll 8
    for (int k = 0; k < HH; k++)
        acc = fmaf(mean[k], __ldg(&W2[(size_t)k * HH + t]), acc);
    t2[t] = acc;
    __syncthreads();

    if (t < HO) {
        float z = lin0b[t];
#pragma unroll 8
        for (int k = 0; k < HH; k++)
            z = fmaf(t2[k], __ldg(&lin0W[(size_t)k * HO + t]), z);
        outz[g * HO + t] = z;
    }
}

// ---------------- triplet head ------------------------------------------------
__global__ void final_kernel(const float* __restrict__ linW,
                             const float* __restrict__ linb,
                             float* __restrict__ out)
{
    __shared__ int s1, s2;
    int g = threadIdx.x;
    if (g == 0) { s1 = 0; s2 = 0; }
    __syncthreads();

    const float* z0 = out;
    const float* z1 = out + GG * HO;
    const float* z2 = out + 2 * GG * HO;
    const float EPS = 1e-6f;

    float dp = 0.f, dn = 0.f;
    float y1 = linb[0], y2 = linb[0];
#pragma unroll 4
    for (int j = 0; j < HO; j++) {
        float a = z0[g * HO + j];
        float b = z1[g * HO + j];
        float c = z2[g * HO + j];
        float e1 = a - b + EPS; dp = fmaf(e1, e1, dp);
        float e2 = a - c + EPS; dn = fmaf(e2, e2, dn);
        float wa = linW[j], wb = linW[HO + j];
        y1 = fmaf(a, wa, fmaf(b, wb, y1));
        y2 = fmaf(a, wa, fmaf(c, wb, y2));
    }
    dp = sqrtf(dp); dn = sqrtf(dn);
    float sp = 1.0f / (1.0f + expf(-y1));
    float sn = 1.0f / (1.0f + expf(-y2));

    const int base = 3 * GG * HO;
    out[base + 1 + g] = sp;
    out[base + 1 + GG + g] = sn;
    if (dn - dp > 0.f) atomicAdd(&s1, 1);
    if (sp - sn > 0.f) atomicAdd(&s2, 1);
    __syncthreads();
    if (g == 0) {
        out[base] = (float)s1;
        out[base + 1 + 2 * GG] = (float)s2;
    }
}

// ---------------- host orchestration ------------------------------------------
extern "C" void kernel_launch(void* const* d_in, const int* in_sizes, int n_in,
                              void* d_out, int out_size)
{
    const float* x[3]     = { (const float*)d_in[0], (const float*)d_in[1], (const float*)d_in[2] };
    const int*   ei[3]    = { (const int*)d_in[3], (const int*)d_in[4], (const int*)d_in[5] };
    const int*   batch[3] = { (const int*)d_in[6], (const int*)d_in[7], (const int*)d_in[8] };
    const float* W0 = (const float*)d_in[9];
    const float* b0 = (const float*)d_in[10];
    const float* W1 = (const float*)d_in[11];
    const float* b1 = (const float*)d_in[12];
    const float* W2 = (const float*)d_in[13];
    const float* b2 = (const float*)d_in[14];
    const float* lin0W = (const float*)d_in[15];
    const float* lin0b = (const float*)d_in[16];
    const float* linW  = (const float*)d_in[17];
    const float* linb  = (const float*)d_in[18];
    float* out = (float*)d_out;

    static cudaStream_t st[3];
    static cudaEvent_t evRoot, evDone[3];
    static bool inited = false;
    if (!inited) {
        for (int i = 0; i < 3; i++) cudaStreamCreateWithFlags(&st[i], cudaStreamNonBlocking);
        cudaEventCreateWithFlags(&evRoot, cudaEventDisableTiming);
        for (int i = 0; i < 3; i++) cudaEventCreateWithFlags(&evDone[i], cudaEventDisableTiming);
        inited = true;
    }

    __half *aptr[3], *aggptr[3], *xhptr[3], *wtbase;
    {
        __half* hb;
        cudaGetSymbolAddress((void**)&hb, g_a);
        for (int i = 0; i < 3; i++) aptr[i] = hb + (size_t)i * NH;
        cudaGetSymbolAddress((void**)&hb, g_agg);
        for (int i = 0; i < 3; i++) aggptr[i] = hb + (size_t)i * NH;
        cudaGetSymbolAddress((void**)&hb, g_xh);
        for (int i = 0; i < 3; i++) xhptr[i] = hb + (size_t)i * NN * FIN;
        cudaGetSymbolAddress((void**)&wtbase, g_wt);
    }
    __half* wt1 = wtbase;                 // [256][256]
    __half* wt0 = wtbase + 256 * HH;      // [256][128]

    dim3 gemmGrid((NN + 127) / 128, HH / 128);
    int  warpBlocks = (int)(((long long)NN * 32 + 255) / 256);
    dim3 pullGrid(warpBlocks, 2);
    const int NB = (NN + 1023) / 1024;
    int  xcvtBlocks = (int)(((size_t)NN * FIN / 4 + 255) / 256);
    int  e4Blocks = (EE / 4 + 255) / 256;

    // weight transposes (shared by all passes) on the capture stream
    wt_kernel<<<(256 * HH + 255) / 256, 256>>>(W1, wt1, HH);
    wt_kernel<<<(256 * FIN + 255) / 256, 256>>>(W0, wt0, FIN);

    cudaEventRecord(evRoot, 0);

    for (int p = 0; p < 3; p++) {
        cudaStream_t s = st[p];
        cudaStreamWaitEvent(s, evRoot, 0);

        const int* srcp = ei[p];
        const int* dstp = ei[p] + EE;

        // ---- per-pass graph prep + x conversion ----
        zero_kernel<<<(NN + 255) / 256, 256, 0, s>>>(p);
        xcvt_kernel<<<xcvtBlocks, 256, 0, s>>>(x[p], xhptr[p]);
        deg_kernel<<<e4Blocks, 256, 0, s>>>(dstp, p);
        dinv_kernel<<<(NN + 255) / 256, 256, 0, s>>>(batch[p], p);
        scan1_kernel<<<NB, 1024, 0, s>>>(p);
        scan2_kernel<<<1, 128, 0, s>>>(p);
        scan3_kernel<<<(NN + 255) / 256, 256, 0, s>>>(p);
        csr_kernel<<<e4Blocks, 256, 0, s>>>(srcp, dstp, p);

        // ---- layer 0: agg0 = Â x (full 128 cols) ; a = relu(agg0 @ W0 + b0)
        pullx_kernel<<<warpBlocks, 256, 0, s>>>(xhptr[p], aggptr[p], p);
        gemmh_kernel<FIN><<<gemmGrid, 256, 0, s>>>(aggptr[p], wt0, b0, aptr[p]);

        // ---- layer 1: agg1 = Â a (2 col halves) ; a = relu(agg1 @ W1 + b1)
        pull_kernel<<<pullGrid, 256, 0, s>>>(aptr[p], aggptr[p], nullptr, 0, p);
        gemmh_kernel<HH><<<gemmGrid, 256, 0, s>>>(aggptr[p], wt1, b1, aptr[p]);

        // ---- layer 2: psum = pool(Â a)  (2 col halves)
        pull_kernel<<<pullGrid, 256, 0, s>>>(aptr[p], nullptr, batch[p], 1, p);

        // ---- z = (psum/cnt @ W2 + b2) @ lin0W + lin0b
        z_kernel<<<GG, 256, 0, s>>>(W2, b2, lin0W, lin0b, out + (size_t)p * GG * HO, p);

        cudaEventRecord(evDone[p], s);
    }

    for (int p = 0; p < 3; p++) cudaStreamWaitEvent(0, evDone[p], 0);

    final_kernel<<<1, GG>>>(linW, linb, out);
}

// round 17
// speedup vs baseline: 1.1021x; 1.0469x over previous
#include <cuda_runtime.h>
#include <cuda_bf16.h>
#include <cuda_fp16.h>
#include <stdint.h>
#include <math.h>

// Problem constants (fixed by the dataset)
#define NN 100000
#define EE 3200000
#define FIN 128
#define HH  256
#define GG  64
#define HO  128   // H/2

typedef unsigned long long u64;

// ---------------- per-pass scratch (static device globals) --------------------
#define NH ((size_t)NN * HH)
__device__ __align__(16) __half g_a  [3][NH];                 // GEMM out, prescaled by dinv
__device__ __align__(16) __half g_agg[3][NH];                 // pull out (GEMM A input)
__device__ __align__(16) __half g_xh [3][(size_t)NN * FIN];   // fp16 dinv-prescaled x
__device__ __align__(16) __half g_wt [256 * HH + 256 * FIN];  // fp16 WT: W1 [256][256], W0 [256][128]
__device__ float g_dinv [3][NN];
__device__ int   g_deg  [3][NN];
__device__ __align__(16) float g_psum[3][GG * HH];
__device__ int   g_pcnt[3][GG];
__device__ int   g_rowptr[3][NN + 1];
__device__ int   g_off[3][NN];
__device__ int   g_bsum[3][128];
__device__ int   g_bsum2[3][128];
__device__ __align__(16) int g_epack[3][EE];    // src index only (prescaled gather)

// ---------------- helpers ----------------------------------------------------
__device__ __forceinline__ void red_add_v4(float4* addr, float4 v) {
    asm volatile("red.global.add.v4.f32 [%0], {%1,%2,%3,%4};"
                 :: "l"(addr), "f"(v.x), "f"(v.y), "f"(v.z), "f"(v.w)
                 : "memory");
}
__device__ __forceinline__ void hadd2(float4& a, uint2 v) {
    float2 x0 = __half22float2(*reinterpret_cast<const __half2*>(&v.x));
    float2 x1 = __half22float2(*reinterpret_cast<const __half2*>(&v.y));
    a.x += x0.x; a.y += x0.y; a.z += x1.x; a.w += x1.y;
}
__device__ __forceinline__ uint2 pack_half4(float4 v) {
    __half2 h0 = __float22half2_rn(make_float2(v.x, v.y));
    __half2 h1 = __float22half2_rn(make_float2(v.z, v.w));
    uint2 s;
    s.x = *reinterpret_cast<uint32_t*>(&h0);
    s.y = *reinterpret_cast<uint32_t*>(&h1);
    return s;
}
__device__ __forceinline__ void mma16816(float* c, const uint32_t* a, const uint32_t* b) {
    asm volatile(
        "mma.sync.aligned.m16n8k16.row.col.f32.f16.f16.f32 "
        "{%0,%1,%2,%3}, {%4,%5,%6,%7}, {%8,%9}, {%0,%1,%2,%3};"
        : "+f"(c[0]), "+f"(c[1]), "+f"(c[2]), "+f"(c[3])
        : "r"(a[0]), "r"(a[1]), "r"(a[2]), "r"(a[3]), "r"(b[0]), "r"(b[1]));
}

// ---------------- per-pass setup ---------------------------------------------
__global__ void zero_kernel(int p) {
    int i = blockIdx.x * blockDim.x + threadIdx.x;
    if (i < NN)      g_deg[p][i] = 0;
    if (i < GG * HH) g_psum[p][i] = 0.f;
    if (i < GG)      g_pcnt[p][i] = 0;
}

// 4 edges per thread (EE % 4 == 0)
__global__ void deg_kernel(const int* __restrict__ dst, int p) {
    int e4 = (blockIdx.x * blockDim.x + threadIdx.x) * 4;
    if (e4 >= EE) return;
    int4 d = *reinterpret_cast<const int4*>(dst + e4);
    atomicAdd(&g_deg[p][d.x], 1);
    atomicAdd(&g_deg[p][d.y], 1);
    atomicAdd(&g_deg[p][d.z], 1);
    atomicAdd(&g_deg[p][d.w], 1);
}

// dinv + fused pcnt
__global__ void dinv_kernel(const int* __restrict__ batch, int p) {
    int i = blockIdx.x * blockDim.x + threadIdx.x;
    if (i < NN) {
        float d = (float)g_deg[p][i] + 1.0f;
        g_dinv[p][i] = rsqrtf(d);
        atomicAdd(&g_pcnt[p][batch[i]], 1);
    }
}

// x fp32 -> fp16, prescaled by dinv[row]  (4 elems/thread, same row)
__global__ void xcvt_kernel(const float* __restrict__ x, __half* __restrict__ xh, int p) {
    size_t i = ((size_t)blockIdx.x * blockDim.x + threadIdx.x) * 4;
    if (i >= (size_t)NN * FIN) return;
    float dv = g_dinv[p][i >> 7];   // FIN = 128
    float4 v = *reinterpret_cast<const float4*>(x + i);
    v.x *= dv; v.y *= dv; v.z *= dv; v.w *= dv;
    *reinterpret_cast<uint2*>(xh + i) = pack_half4(v);
}

// W [K][256] fp32 -> WT [256][K] fp16
__global__ void wt_kernel(const float* __restrict__ W, __half* __restrict__ WT, int K) {
    int idx = blockIdx.x * blockDim.x + threadIdx.x;
    if (idx >= 256 * K) return;
    int n = idx / K, k = idx % K;
    WT[idx] = __float2half(W[(size_t)k * 256 + n]);
}

// ---------------- exclusive scan of deg -> rowptr ------------------------------
__global__ void scan1_kernel(int p) {
    __shared__ int s[1024];
    int t = threadIdx.x;
    int i = blockIdx.x * 1024 + t;
    int v = (i < NN) ? g_deg[p][i] : 0;
    int x = v;
    s[t] = x;
    __syncthreads();
#pragma unroll
    for (int off = 1; off < 1024; off <<= 1) {
        int y = (t >= off) ? s[t - off] : 0;
        __syncthreads();
        x += y;
        s[t] = x;
        __syncthreads();
    }
    if (i < NN) g_rowptr[p][i] = x - v;
    if (t == 1023) g_bsum[p][blockIdx.x] = x;
}

__global__ void scan2_kernel(int p) {
    __shared__ int s[128];
    int t = threadIdx.x;
    const int NB = (NN + 1023) >> 10;
    int v = (t < NB) ? g_bsum[p][t] : 0;
    int x = v;
    s[t] = x;
    __syncthreads();
#pragma unroll
    for (int off = 1; off < 128; off <<= 1) {
        int y = (t >= off) ? s[t - off] : 0;
        __syncthreads();
        x += y;
        s[t] = x;
        __syncthreads();
    }
    g_bsum2[p][t] = x - v;
}

// rowptr finalize + seed g_off (csr then needs ONE atomic, no rowptr gather)
__global__ void scan3_kernel(int p) {
    int i = blockIdx.x * blockDim.x + threadIdx.x;
    if (i < NN) {
        int rp = g_rowptr[p][i] + g_bsum2[p][i >> 10];
        g_rowptr[p][i] = rp;
        g_off[p][i] = rp;
    }
    if (i == 0) g_rowptr[p][NN] = EE;
}

// 4 edges per thread; record = bare src index
__global__ void csr_kernel(const int* __restrict__ src, const int* __restrict__ dst, int p) {
    int e4 = (blockIdx.x * blockDim.x + threadIdx.x) * 4;
    if (e4 >= EE) return;
    int4 s4 = *reinterpret_cast<const int4*>(src + e4);
    int4 d4 = *reinterpret_cast<const int4*>(dst + e4);
    int ss[4] = {s4.x, s4.y, s4.z, s4.w};
    int dd[4] = {d4.x, d4.y, d4.z, d4.w};
#pragma unroll
    for (int j = 0; j < 4; j++) {
        int pos = atomicAdd(&g_off[p][dd[j]], 1);
        g_epack[p][pos] = ss[j];
    }
}

// ---------------- layer-0 aggregation: agg0[n] = dinv[n]*(x̃[n]+Σ x̃[s]) --------
__global__ void __launch_bounds__(256)
pullx_kernel(const __half* __restrict__ xh, __half* __restrict__ agg, int p)
{
    int n = (int)((blockIdx.x * (unsigned)blockDim.x + threadIdx.x) >> 5);
    int lane = threadIdx.x & 31;
    if (n >= NN) return;
    int c = lane * 4;

    float4 acc = make_float4(0.f, 0.f, 0.f, 0.f);
    hadd2(acc, *reinterpret_cast<const uint2*>(xh + (size_t)n * FIN + c));

    int e = g_rowptr[p][n];
    int end = g_rowptr[p][n + 1];
    const int* ep = g_epack[p];

    while ((e & 3) && e < end) {
        hadd2(acc, *reinterpret_cast<const uint2*>(xh + (size_t)ep[e] * FIN + c));
        e++;
    }
    for (; e + 7 < end; e += 8) {
        int4 q0 = *reinterpret_cast<const int4*>(&ep[e]);
        int4 q1 = *reinterpret_cast<const int4*>(&ep[e + 4]);
        uint2 v[8];
        v[0] = *reinterpret_cast<const uint2*>(xh + (size_t)q0.x * FIN + c);
        v[1] = *reinterpret_cast<const uint2*>(xh + (size_t)q0.y * FIN + c);
        v[2] = *reinterpret_cast<const uint2*>(xh + (size_t)q0.z * FIN + c);
        v[3] = *reinterpret_cast<const uint2*>(xh + (size_t)q0.w * FIN + c);
        v[4] = *reinterpret_cast<const uint2*>(xh + (size_t)q1.x * FIN + c);
        v[5] = *reinterpret_cast<const uint2*>(xh + (size_t)q1.y * FIN + c);
        v[6] = *reinterpret_cast<const uint2*>(xh + (size_t)q1.z * FIN + c);
        v[7] = *reinterpret_cast<const uint2*>(xh + (size_t)q1.w * FIN + c);
#pragma unroll
        for (int j = 0; j < 8; j++) hadd2(acc, v[j]);
    }
    for (; e < end; e++)
        hadd2(acc, *reinterpret_cast<const uint2*>(xh + (size_t)ep[e] * FIN + c));

    float dv = g_dinv[p][n];
    acc.x *= dv; acc.y *= dv; acc.z *= dv; acc.w *= dv;
    *reinterpret_cast<uint2*>(agg + (size_t)n * FIN + c) = pack_half4(acc);
}

// ---------------- GEMM via HMMA: out = dinv[row]*relu(A @ W + bias) -----------
template <int K>
__global__ void __launch_bounds__(256, 2)
gemmh_kernel(const __half* __restrict__ A, const __half* __restrict__ WT,
             const float* __restrict__ bias, __half* __restrict__ Hout, int p)
{
    __shared__ uint32_t As2[16 * 136];
    __shared__ uint32_t Bs2[16 * 136];

    const int t = threadIdx.x;
    const int lane = t & 31;
    const int wid = t >> 5;
    const int g = lane >> 2;
    const int q = lane & 3;
    const int wm = wid & 3;
    const int wn = wid >> 2;
    const int rowBase = blockIdx.x * 128;
    const int colBase = blockIdx.y * 128;

    const int sr = t >> 1;
    const int sh = t & 1;

    float acc[2][8][4];
#pragma unroll
    for (int mt = 0; mt < 2; mt++)
#pragma unroll
        for (int nt = 0; nt < 8; nt++)
#pragma unroll
            for (int i = 0; i < 4; i++) acc[mt][nt][i] = 0.f;

    const int arow = rowBase + sr;
    uint4 pa0, pa1, pb0, pb1;
    {
        pa0 = make_uint4(0u,0u,0u,0u); pa1 = pa0;
        if (arow < NN) {
            const __half* ap = A + (size_t)arow * K + sh * 16;
            pa0 = *reinterpret_cast<const uint4*>(ap);
            pa1 = *reinterpret_cast<const uint4*>(ap + 8);
        }
        const __half* bp = WT + (size_t)(colBase + sr) * K + sh * 16;
        pb0 = *reinterpret_cast<const uint4*>(bp);
        pb1 = *reinterpret_cast<const uint4*>(bp + 8);
    }

    for (int kb = 0; kb < K; kb += 32) {
        {
            uint32_t av[8] = {pa0.x, pa0.y, pa0.z, pa0.w, pa1.x, pa1.y, pa1.z, pa1.w};
            uint32_t bv[8] = {pb0.x, pb0.y, pb0.z, pb0.w, pb1.x, pb1.y, pb1.z, pb1.w};
            int kp0 = sh * 8;
#pragma unroll
            for (int j = 0; j < 8; j++) {
                As2[(kp0 + j) * 136 + sr] = av[j];
                Bs2[(kp0 + j) * 136 + sr] = bv[j];
            }
        }
        __syncthreads();

        if (kb + 32 < K) {
            int kn = kb + 32;
            pa0 = make_uint4(0u,0u,0u,0u); pa1 = pa0;
            if (arow < NN) {
                const __half* ap = A + (size_t)arow * K + kn + sh * 16;
                pa0 = *reinterpret_cast<const uint4*>(ap);
                pa1 = *reinterpret_cast<const uint4*>(ap + 8);
            }
            const __half* bp = WT + (size_t)(colBase + sr) * K + kn + sh * 16;
            pb0 = *reinterpret_cast<const uint4*>(bp);
            pb1 = *reinterpret_cast<const uint4*>(bp + 8);
        }

#pragma unroll
        for (int s = 0; s < 2; s++) {
            int kp = s * 8 + q;
            uint32_t afr[2][4];
#pragma unroll
            for (int mt = 0; mt < 2; mt++) {
                int R = wm * 32 + mt * 16;
                afr[mt][0] = As2[kp * 136 + R + g];
                afr[mt][1] = As2[kp * 136 + R + 8 + g];
                afr[mt][2] = As2[(kp + 4) * 136 + R + g];
                afr[mt][3] = As2[(kp + 4) * 136 + R + 8 + g];
            }
            uint32_t bfr[8][2];
#pragma unroll
            for (int nt = 0; nt < 8; nt++) {
                int nc = wn * 64 + nt * 8 + g;
                bfr[nt][0] = Bs2[kp * 136 + nc];
                bfr[nt][1] = Bs2[(kp + 4) * 136 + nc];
            }
#pragma unroll
            for (int mt = 0; mt < 2; mt++)
#pragma unroll
                for (int nt = 0; nt < 8; nt++)
                    mma16816(acc[mt][nt], afr[mt], bfr[nt]);
        }
        __syncthreads();
    }

#pragma unroll
    for (int mt = 0; mt < 2; mt++) {
        int row0 = rowBase + wm * 32 + mt * 16 + g;
        int row1 = row0 + 8;
        float dv0 = (row0 < NN) ? g_dinv[p][row0] : 0.f;
        float dv1 = (row1 < NN) ? g_dinv[p][row1] : 0.f;
#pragma unroll
        for (int nt = 0; nt < 8; nt++) {
            int col = colBase + wn * 64 + nt * 8 + q * 2;
            float2 bb = *reinterpret_cast<const float2*>(bias + col);
            if (row0 < NN) {
                float vx = dv0 * fmaxf(acc[mt][nt][0] + bb.x, 0.f);
                float vy = dv0 * fmaxf(acc[mt][nt][1] + bb.y, 0.f);
                __half2 h = __float22half2_rn(make_float2(vx, vy));
                *reinterpret_cast<uint32_t*>(Hout + (size_t)row0 * HH + col) =
                    *reinterpret_cast<uint32_t*>(&h);
            }
            if (row1 < NN) {
                float vx = dv1 * fmaxf(acc[mt][nt][2] + bb.x, 0.f);
                float vy = dv1 * fmaxf(acc[mt][nt][3] + bb.y, 0.f);
                __half2 h = __float22half2_rn(make_float2(vx, vy));
                *reinterpret_cast<uint32_t*>(Hout + (size_t)row1 * HH + col) =
                    *reinterpret_cast<uint32_t*>(&h);
            }
        }
    }
}

// ---------------- pull (column-half): agg[n] = dinv[n]*(ã[n]+Σ ã[s]) -----------
// blockIdx.y selects the 128-col half. doPool==1: pooled into psum only.
__global__ void __launch_bounds__(256)
pull_kernel(const __half* __restrict__ a, __half* __restrict__ agg,
            const int* __restrict__ batch, int doPool, int p)
{
    int n = (int)((blockIdx.x * (unsigned)blockDim.x + threadIdx.x) >> 5);
    int lane = threadIdx.x & 31;
    if (n >= NN) return;
    int c = blockIdx.y * 128 + lane * 4;

    float4 acc = make_float4(0.f, 0.f, 0.f, 0.f);
    hadd2(acc, *reinterpret_cast<const uint2*>(a + (size_t)n * HH + c));

    int e = g_rowptr[p][n];
    int end = g_rowptr[p][n + 1];
    const int* ep = g_epack[p];

    while ((e & 3) && e < end) {
        hadd2(acc, *reinterpret_cast<const uint2*>(a + (size_t)ep[e] * HH + c));
        e++;
    }
    for (; e + 7 < end; e += 8) {
        int4 q0 = *reinterpret_cast<const int4*>(&ep[e]);
        int4 q1 = *reinterpret_cast<const int4*>(&ep[e + 4]);
        uint2 v[8];
        v[0] = *reinterpret_cast<const uint2*>(a + (size_t)q0.x * HH + c);
        v[1] = *reinterpret_cast<const uint2*>(a + (size_t)q0.y * HH + c);
        v[2] = *reinterpret_cast<const uint2*>(a + (size_t)q0.z * HH + c);
        v[3] = *reinterpret_cast<const uint2*>(a + (size_t)q0.w * HH + c);
        v[4] = *reinterpret_cast<const uint2*>(a + (size_t)q1.x * HH + c);
        v[5] = *reinterpret_cast<const uint2*>(a + (size_t)q1.y * HH + c);
        v[6] = *reinterpret_cast<const uint2*>(a + (size_t)q1.z * HH + c);
        v[7] = *reinterpret_cast<const uint2*>(a + (size_t)q1.w * HH + c);
#pragma unroll
        for (int j = 0; j < 8; j++) hadd2(acc, v[j]);
    }
    for (; e < end; e++)
        hadd2(acc, *reinterpret_cast<const uint2*>(a + (size_t)ep[e] * HH + c));

    float dv = g_dinv[p][n];
    acc.x *= dv; acc.y *= dv; acc.z *= dv; acc.w *= dv;

    if (!doPool) {
        *reinterpret_cast<uint2*>(agg + (size_t)n * HH + c) = pack_half4(acc);
    } else {
        int g = __ldg(&batch[n]);
        red_add_v4(reinterpret_cast<float4*>(g_psum[p] + g * HH + c), acc);
    }
}

// ---------------- z: mean = psum/cnt ; t2 = mean@W2 + b2 ; z = t2@lin0W + lin0b -
__global__ void __launch_bounds__(256)
z_kernel(const float* __restrict__ W2, const float* __restrict__ b2,
         const float* __restrict__ lin0W, const float* __restrict__ lin0b,
         float* __restrict__ outz, int p)
{
    __shared__ float mean[HH];
    __shared__ float t2[HH];
    int g = blockIdx.x;
    int t = threadIdx.x;
    float cnt = fmaxf((float)g_pcnt[p][g], 1.0f);
    mean[t] = g_psum[p][g * HH + t] / cnt;
    __syncthreads();

    float acc = b2[t];
#pragma unroll 8
    for (int k = 0; k < HH; k++)
        acc = fmaf(mean[k], __ldg(&W2[(size_t)k * HH + t]), acc);
    t2[t] = acc;
    __syncthreads();

    if (t < HO) {
        float z = lin0b[t];
#pragma unroll 8
        for (int k = 0; k < HH; k++)
            z = fmaf(t2[k], __ldg(&lin0W[(size_t)k * HO + t]), z);
        outz[g * HO + t] = z;
    }
}

// ---------------- triplet head ------------------------------------------------
__global__ void final_kernel(const float* __restrict__ linW,
                             const float* __restrict__ linb,
                             float* __restrict__ out)
{
    __shared__ int s1, s2;
    int g = threadIdx.x;
    if (g == 0) { s1 = 0; s2 = 0; }
    __syncthreads();

    const float* z0 = out;
    const float* z1 = out + GG * HO;
    const float* z2 = out + 2 * GG * HO;
    const float EPS = 1e-6f;

    float dp = 0.f, dn = 0.f;
    float y1 = linb[0], y2 = linb[0];
#pragma unroll 4
    for (int j = 0; j < HO; j++) {
        float a = z0[g * HO + j];
        float b = z1[g * HO + j];
        float c = z2[g * HO + j];
        float e1 = a - b + EPS; dp = fmaf(e1, e1, dp);
        float e2 = a - c + EPS; dn = fmaf(e2, e2, dn);
        float wa = linW[j], wb = linW[HO + j];
        y1 = fmaf(a, wa, fmaf(b, wb, y1));
        y2 = fmaf(a, wa, fmaf(c, wb, y2));
    }
    dp = sqrtf(dp); dn = sqrtf(dn);
    float sp = 1.0f / (1.0f + expf(-y1));
    float sn = 1.0f / (1.0f + expf(-y2));

    const int base = 3 * GG * HO;
    out[base + 1 + g] = sp;
    out[base + 1 + GG + g] = sn;
    if (dn - dp > 0.f) atomicAdd(&s1, 1);
    if (sp - sn > 0.f) atomicAdd(&s2, 1);
    __syncthreads();
    if (g == 0) {
        out[base] = (float)s1;
        out[base + 1 + 2 * GG] = (float)s2;
    }
}

// ---------------- host orchestration ------------------------------------------
extern "C" void kernel_launch(void* const* d_in, const int* in_sizes, int n_in,
                              void* d_out, int out_size)
{
    const float* x[3]     = { (const float*)d_in[0], (const float*)d_in[1], (const float*)d_in[2] };
    const int*   ei[3]    = { (const int*)d_in[3], (const int*)d_in[4], (const int*)d_in[5] };
    const int*   batch[3] = { (const int*)d_in[6], (const int*)d_in[7], (const int*)d_in[8] };
    const float* W0 = (const float*)d_in[9];
    const float* b0 = (const float*)d_in[10];
    const float* W1 = (const float*)d_in[11];
    const float* b1 = (const float*)d_in[12];
    const float* W2 = (const float*)d_in[13];
    const float* b2 = (const float*)d_in[14];
    const float* lin0W = (const float*)d_in[15];
    const float* lin0b = (const float*)d_in[16];
    const float* linW  = (const float*)d_in[17];
    const float* linb  = (const float*)d_in[18];
    float* out = (float*)d_out;

    static cudaStream_t st[3];
    static cudaEvent_t evRoot, evDone[3];
    static bool inited = false;
    if (!inited) {
        for (int i = 0; i < 3; i++) cudaStreamCreateWithFlags(&st[i], cudaStreamNonBlocking);
        cudaEventCreateWithFlags(&evRoot, cudaEventDisableTiming);
        for (int i = 0; i < 3; i++) cudaEventCreateWithFlags(&evDone[i], cudaEventDisableTiming);
        inited = true;
    }

    __half *aptr[3], *aggptr[3], *xhptr[3], *wtbase;
    {
        __half* hb;
        cudaGetSymbolAddress((void**)&hb, g_a);
        for (int i = 0; i < 3; i++) aptr[i] = hb + (size_t)i * NH;
        cudaGetSymbolAddress((void**)&hb, g_agg);
        for (int i = 0; i < 3; i++) aggptr[i] = hb + (size_t)i * NH;
        cudaGetSymbolAddress((void**)&hb, g_xh);
        for (int i = 0; i < 3; i++) xhptr[i] = hb + (size_t)i * NN * FIN;
        cudaGetSymbolAddress((void**)&wtbase, g_wt);
    }
    __half* wt1 = wtbase;                 // [256][256]
    __half* wt0 = wtbase + 256 * HH;      // [256][128]

    dim3 gemmGrid((NN + 127) / 128, HH / 128);
    int  warpBlocks = (int)(((long long)NN * 32 + 255) / 256);
    dim3 pullGrid(warpBlocks, 2);
    const int NB = (NN + 1023) / 1024;
    int  xcvtBlocks = (int)(((size_t)NN * FIN / 4 + 255) / 256);
    int  e4Blocks = (EE / 4 + 255) / 256;

    // weight transposes (shared by all passes) on the capture stream
    wt_kernel<<<(256 * HH + 255) / 256, 256>>>(W1, wt1, HH);
    wt_kernel<<<(256 * FIN + 255) / 256, 256>>>(W0, wt0, FIN);

    cudaEventRecord(evRoot, 0);

    for (int p = 0; p < 3; p++) {
        cudaStream_t s = st[p];
        cudaStreamWaitEvent(s, evRoot, 0);

        const int* srcp = ei[p];
        const int* dstp = ei[p] + EE;

        // ---- per-pass graph prep (xcvt after dinv: prescale needs dinv) ----
        zero_kernel<<<(NN + 255) / 256, 256, 0, s>>>(p);
        deg_kernel<<<e4Blocks, 256, 0, s>>>(dstp, p);
        dinv_kernel<<<(NN + 255) / 256, 256, 0, s>>>(batch[p], p);
        xcvt_kernel<<<xcvtBlocks, 256, 0, s>>>(x[p], xhptr[p], p);
        scan1_kernel<<<NB, 1024, 0, s>>>(p);
        scan2_kernel<<<1, 128, 0, s>>>(p);
        scan3_kernel<<<(NN + 255) / 256, 256, 0, s>>>(p);
        csr_kernel<<<e4Blocks, 256, 0, s>>>(srcp, dstp, p);

        // ---- layer 0: agg0 = Â x ; ã = dinv*relu(agg0 @ W0 + b0)
        pullx_kernel<<<warpBlocks, 256, 0, s>>>(xhptr[p], aggptr[p], p);
        gemmh_kernel<FIN><<<gemmGrid, 256, 0, s>>>(aggptr[p], wt0, b0, aptr[p], p);

        // ---- layer 1: agg1 = Â relu(a) ; ã = dinv*relu(agg1 @ W1 + b1)
        pull_kernel<<<pullGrid, 256, 0, s>>>(aptr[p], aggptr[p], nullptr, 0, p);
        gemmh_kernel<HH><<<gemmGrid, 256, 0, s>>>(aggptr[p], wt1, b1, aptr[p], p);

        // ---- layer 2: psum = pool(Â relu(a))
        pull_kernel<<<pullGrid, 256, 0, s>>>(aptr[p], nullptr, batch[p], 1, p);

        // ---- z = (psum/cnt @ W2 + b2) @ lin0W + lin0b
        z_kernel<<<GG, 256, 0, s>>>(W2, b2, lin0W, lin0b, out + (size_t)p * GG * HO, p);

        cudaEventRecord(evDone[p], s);
    }

    for (int p = 0; p < 3; p++) cudaStreamWaitEvent(0, evDone[p], 0);

    final_kernel<<<1, GG>>>(linW, linb, out);
}